// round 9
// baseline (speedup 1.0000x reference)
#include <cuda_runtime.h>
#include <cuda_fp16.h>
#include <math.h>
#include <stdint.h>

constexpr int Nn = 100000;
constexpr int Ed = 1600000;
constexpr int DIN = 64;
constexpr int NB_SCAN = (Nn + 1023) / 1024;   // 98
constexpr int NTILES  = (Nn + 127) / 128;     // 782
constexpr int TILES_A = 400;                  // first-half tiles
constexpr int NH      = TILES_A * 128;        // 51200 first-half nodes

// ---- scratch (device globals; no allocation allowed) ----------------------
__device__ __half g_yA[(size_t)Nn * 64];
__device__ float  g_pA[(size_t)Nn * 64];
__device__ __half g_yB[(size_t)Nn * 64];
__device__ float  g_pB[(size_t)Nn * 64];
__device__ float  g_h0[(size_t)Nn * 64];
__device__ float  g_h1[(size_t)Nn * 64];
__device__ int    g_csr_src[Ed];
__device__ int    g_rowptr[Nn];
__device__ int    g_rowloc[Nn];
__device__ int    g_cursor[Nn];
__device__ int    g_deg[Nn];
__device__ float  g_invdeg[Nn];
__device__ int    g_bsum[NB_SCAN];

// ---------------------------------------------------------------------------
__global__ void zero_deg_kernel() {
    int i = blockIdx.x * blockDim.x + threadIdx.x;
    if (i < Nn) g_deg[i] = 0;
}

__global__ void deg_kernel(const int* __restrict__ dst) {
    int e4 = blockIdx.x * blockDim.x + threadIdx.x;
    if (e4 < Ed / 4) {
        int4 d = __ldg(reinterpret_cast<const int4*>(dst) + e4);
        atomicAdd(&g_deg[d.x], 1);
        atomicAdd(&g_deg[d.y], 1);
        atomicAdd(&g_deg[d.z], 1);
        atomicAdd(&g_deg[d.w], 1);
    }
}

// warp-shuffle block scan (2 barriers instead of 20)
__global__ void scanA_kernel() {
    __shared__ int wsum[32];
    int tid = threadIdx.x;
    int i = blockIdx.x * 1024 + tid;
    int v = (i < Nn) ? g_deg[i] : 0;
    if (i < Nn) g_invdeg[i] = 1.0f / fmaxf((float)v, 1.0f);
    int lane = tid & 31, wid = tid >> 5;
    int x = v;
#pragma unroll
    for (int o = 1; o < 32; o <<= 1) {
        int t = __shfl_up_sync(0xFFFFFFFFu, x, o);
        if (lane >= o) x += t;
    }
    if (lane == 31) wsum[wid] = x;
    __syncthreads();
    if (wid == 0) {
        int s = wsum[lane];
#pragma unroll
        for (int o = 1; o < 32; o <<= 1) {
            int t = __shfl_up_sync(0xFFFFFFFFu, s, o);
            if (lane >= o) s += t;
        }
        wsum[lane] = s;
    }
    __syncthreads();
    int incl = x + ((wid > 0) ? wsum[wid - 1] : 0);
    if (i < Nn) g_rowloc[i] = incl - v;
    if (tid == 1023) g_bsum[blockIdx.x] = incl;
}

__global__ void scanC_kernel() {
    __shared__ int sb[NB_SCAN];
    int tid = threadIdx.x;
    for (int j = tid; j < NB_SCAN; j += 256) sb[j] = g_bsum[j];
    __syncthreads();
    int i = blockIdx.x * 256 + tid;
    if (i < Nn) {
        int blk = i >> 10;
        int off = 0;
        for (int j = 0; j < blk; j++) off += sb[j];
        int r = g_rowloc[i] + off;
        g_rowptr[i] = r;
        g_cursor[i] = r;
    }
}

__global__ void fill_kernel(const int* __restrict__ src,
                            const int* __restrict__ dst) {
    int e4 = blockIdx.x * blockDim.x + threadIdx.x;
    if (e4 < Ed / 4) {
        int4 s = __ldg(reinterpret_cast<const int4*>(src) + e4);
        int4 d = __ldg(reinterpret_cast<const int4*>(dst) + e4);
        g_csr_src[atomicAdd(&g_cursor[d.x], 1)] = s.x;
        g_csr_src[atomicAdd(&g_cursor[d.y], 1)] = s.y;
        g_csr_src[atomicAdd(&g_cursor[d.z], 1)] = s.z;
        g_csr_src[atomicAdd(&g_cursor[d.w], 1)] = s.w;
    }
}

// ---------------------------------------------------------------------------
__device__ __forceinline__ uint32_t f2tf32(float x) {
    uint32_t r;
    asm("cvt.rna.tf32.f32 %0, %1;" : "=r"(r) : "f"(x));
    return r;
}

__device__ __forceinline__ void mma_tf32(float c[4], const uint32_t a[4],
                                         const uint32_t b0, const uint32_t b1) {
    asm volatile(
        "mma.sync.aligned.m16n8k8.row.col.f32.tf32.tf32.f32 "
        "{%0,%1,%2,%3}, {%4,%5,%6,%7}, {%8,%9}, {%0,%1,%2,%3};"
        : "+f"(c[0]), "+f"(c[1]), "+f"(c[2]), "+f"(c[3])
        : "r"(a[0]), "r"(a[1]), "r"(a[2]), "r"(a[3]), "r"(b0), "r"(b1));
}

__device__ __forceinline__ uint32_t s2u(const void* p) {
    uint32_t a;
    asm("{.reg .u64 t; cvta.to.shared.u64 t, %1; cvt.u32.u64 %0, t;}"
        : "=r"(a) : "l"(p));
    return a;
}

__device__ __forceinline__ void cp16(uint32_t dst, const void* src) {
    asm volatile("cp.async.cg.shared.global [%0], [%1], 16;"
                 :: "r"(dst), "l"(src));
}

// ---------------------------------------------------------------------------
// Transform via tf32 tensor cores over tile range [tile_begin, tile_end).
// C[128 x 2*DOUT] = H[128 x 64] @ [Wl | Wr]; left->y(fp16), right->p(fp32,+bl).
// ---------------------------------------------------------------------------
template <int DOUT>
__global__ void transform_mma(const float* __restrict__ hin,
                              const float* __restrict__ Wl,
                              const float* __restrict__ bl,
                              const float* __restrict__ Wr,
                              __half* __restrict__ y,
                              float* __restrict__ p,
                              int tile_begin, int tile_end) {
    constexpr int NC  = 2 * DOUT;
    constexpr int NT  = NC / 8;
    constexpr int NQ  = NT / 2;
    constexpr int SHP = 68;
    constexpr int WF_WORDS = 8 * NQ * 32 * 4;

    extern __shared__ uint32_t smem[];
    uint32_t* sWf = smem;
    float* sHA = (float*)(smem + WF_WORDS);
    float* sHB = sHA + 128 * SHP;
    float* sbl = sHB + 128 * SHP;

    const int tid = threadIdx.x;
    const int w   = tid >> 5;
    const int l   = tid & 31;
    const int g   = l >> 2;
    const int tig = l & 3;

    for (int idx = tid; idx < 8 * NQ * 32; idx += 256) {
        int ks  = idx / (NQ * 32);
        int rem = idx - ks * (NQ * 32);
        int q   = rem >> 5;
        int ll  = rem & 31;
        int gg  = ll >> 2;
        int tt  = ll & 3;
        int k_lo = ks * 8 + tt;
        int k_hi = k_lo + 4;
        uint4 frag;
        {
            int cc = (2 * q) * 8 + gg;
            const float* basev = (cc < DOUT) ? (Wl + cc) : (Wr + cc - DOUT);
            frag.x = f2tf32(__ldg(basev + k_lo * DOUT));
            frag.y = f2tf32(__ldg(basev + k_hi * DOUT));
        }
        {
            int cc = (2 * q + 1) * 8 + gg;
            const float* basev = (cc < DOUT) ? (Wl + cc) : (Wr + cc - DOUT);
            frag.z = f2tf32(__ldg(basev + k_lo * DOUT));
            frag.w = f2tf32(__ldg(basev + k_hi * DOUT));
        }
        reinterpret_cast<uint4*>(sWf)[idx] = frag;
    }
    if (tid < DOUT) sbl[tid] = bl[tid];

    const uint4* wf = reinterpret_cast<const uint4*>(sWf) + l;

    auto stage = [&](int tile, float* buf) {
        if (tile < tile_end) {
            const int base = tile * 128;
            const uint32_t bufu = s2u(buf);
            for (int v = tid; v < 2048; v += 256) {
                int r  = v >> 4;
                int cb = (v & 15) * 16;
                int node = base + r;
                uint32_t d = bufu + (uint32_t)(r * (SHP * 4) + cb);
                if (node < Nn)
                    cp16(d, (const char*)(hin + (size_t)node * 64) + cb);
                else
                    *reinterpret_cast<float4*>((char*)buf + r * (SHP * 4) + cb) =
                        make_float4(0.f, 0.f, 0.f, 0.f);
            }
        }
        asm volatile("cp.async.commit_group;");
    };

    float* cur = sHA;
    float* nxt = sHB;
    int tile = tile_begin + blockIdx.x;
    stage(tile, cur);

    for (; tile < tile_end; tile += gridDim.x) {
        stage(tile + gridDim.x, nxt);
        asm volatile("cp.async.wait_group 1;");
        __syncthreads();

        float c[NT][4];
#pragma unroll
        for (int nt = 0; nt < NT; nt++) {
            c[nt][0] = 0.f; c[nt][1] = 0.f; c[nt][2] = 0.f; c[nt][3] = 0.f;
        }

        const float* sHr0 = cur + (16 * w + g) * SHP;
        const float* sHr1 = sHr0 + 8 * SHP;

#pragma unroll
        for (int ks = 0; ks < 8; ks++) {
            const int k0 = ks * 8;
            uint32_t a[4];
            a[0] = f2tf32(sHr0[k0 + tig]);
            a[1] = f2tf32(sHr1[k0 + tig]);
            a[2] = f2tf32(sHr0[k0 + tig + 4]);
            a[3] = f2tf32(sHr1[k0 + tig + 4]);
#pragma unroll
            for (int q = 0; q < NQ; q++) {
                uint4 b = wf[(ks * NQ + q) * 32];
                mma_tf32(c[2 * q],     a, b.x, b.y);
                mma_tf32(c[2 * q + 1], a, b.z, b.w);
            }
        }

        const int base = tile * 128;
        const int node0 = base + 16 * w + g;
        const int node1 = node0 + 8;
#pragma unroll
        for (int nt = 0; nt < NT; nt++) {
            int col = nt * 8 + 2 * tig;
            if (col < DOUT) {
                if (node0 < Nn)
                    *reinterpret_cast<__half2*>(y + (size_t)node0 * DOUT + col) =
                        __floats2half2_rn(c[nt][0], c[nt][1]);
                if (node1 < Nn)
                    *reinterpret_cast<__half2*>(y + (size_t)node1 * DOUT + col) =
                        __floats2half2_rn(c[nt][2], c[nt][3]);
            } else {
                int pc = col - DOUT;
                float b0 = sbl[pc], b1 = sbl[pc + 1];
                if (node0 < Nn)
                    *reinterpret_cast<float2*>(p + (size_t)node0 * DOUT + pc) =
                        make_float2(c[nt][0] + b0, c[nt][1] + b1);
                if (node1 < Nn)
                    *reinterpret_cast<float2*>(p + (size_t)node1 * DOUT + pc) =
                        make_float2(c[nt][2] + b0, c[nt][3] + b1);
            }
        }
        __syncthreads();
        float* t = cur; cur = nxt; nxt = t;
    }
}

// ---------------------------------------------------------------------------
// Gather over node range [node_begin, node_end).
// ---------------------------------------------------------------------------
template <int DOUT, bool RELU, bool FINAL>
__global__ void gather_kernel(const __half* __restrict__ y,
                              const float* __restrict__ p,
                              float* __restrict__ out,
                              int node_begin, int node_end) {
    int w = node_begin + ((blockIdx.x * blockDim.x + threadIdx.x) >> 5);
    int lane = threadIdx.x & 31;
    if (w >= node_end) return;
    const bool act = (2 * lane) < DOUT;

    const int start = g_rowptr[w];
    const int cnt   = g_deg[w];
    const int* __restrict__ idxp = g_csr_src + start;
    const __half2* __restrict__ y2 = reinterpret_cast<const __half2*>(y);
    constexpr int STRIDE = DOUT / 2;

    float2 acc = make_float2(0.f, 0.f);
    int i = 0;
    for (; i + 8 <= cnt; i += 8) {
        int s0 = __ldg(idxp + i + 0);
        int s1 = __ldg(idxp + i + 1);
        int s2 = __ldg(idxp + i + 2);
        int s3 = __ldg(idxp + i + 3);
        int s4 = __ldg(idxp + i + 4);
        int s5 = __ldg(idxp + i + 5);
        int s6 = __ldg(idxp + i + 6);
        int s7 = __ldg(idxp + i + 7);
        if (act) {
            __half2 v0 = __ldg(y2 + (size_t)s0 * STRIDE + lane);
            __half2 v1 = __ldg(y2 + (size_t)s1 * STRIDE + lane);
            __half2 v2 = __ldg(y2 + (size_t)s2 * STRIDE + lane);
            __half2 v3 = __ldg(y2 + (size_t)s3 * STRIDE + lane);
            __half2 v4 = __ldg(y2 + (size_t)s4 * STRIDE + lane);
            __half2 v5 = __ldg(y2 + (size_t)s5 * STRIDE + lane);
            __half2 v6 = __ldg(y2 + (size_t)s6 * STRIDE + lane);
            __half2 v7 = __ldg(y2 + (size_t)s7 * STRIDE + lane);
            float2 f0 = __half22float2(v0), f1 = __half22float2(v1);
            float2 f2 = __half22float2(v2), f3 = __half22float2(v3);
            float2 f4 = __half22float2(v4), f5 = __half22float2(v5);
            float2 f6 = __half22float2(v6), f7 = __half22float2(v7);
            acc.x += ((f0.x + f1.x) + (f2.x + f3.x)) + ((f4.x + f5.x) + (f6.x + f7.x));
            acc.y += ((f0.y + f1.y) + (f2.y + f3.y)) + ((f4.y + f5.y) + (f6.y + f7.y));
        }
    }
    for (; i < cnt; i++) {
        int s = __ldg(idxp + i);
        if (act) {
            float2 f = __half22float2(__ldg(y2 + (size_t)s * STRIDE + lane));
            acc.x += f.x;
            acc.y += f.y;
        }
    }

    float invd = g_invdeg[w];
    float2 o = make_float2(0.f, 0.f);
    if (act) {
        float2 pp = *reinterpret_cast<const float2*>(p + (size_t)w * DOUT + 2 * lane);
        o.x = fmaf(acc.x, invd, pp.x);
        o.y = fmaf(acc.y, invd, pp.y);
        if (RELU) { o.x = fmaxf(o.x, 0.f); o.y = fmaxf(o.y, 0.f); }
    }

    if (FINAL) {
        float m = act ? fmaxf(o.x, o.y) : -INFINITY;
#pragma unroll
        for (int off = 16; off; off >>= 1) m = fmaxf(m, __shfl_xor_sync(0xFFFFFFFFu, m, off));
        float s = act ? (expf(o.x - m) + expf(o.y - m)) : 0.f;
#pragma unroll
        for (int off = 16; off; off >>= 1) s += __shfl_xor_sync(0xFFFFFFFFu, s, off);
        float lse = m + logf(s);
        o.x -= lse;
        o.y -= lse;
    }
    if (act)
        *reinterpret_cast<float2*>(out + (size_t)w * DOUT + 2 * lane) = o;
}

// ---------------------------------------------------------------------------
extern "C" void kernel_launch(void* const* d_in, const int* in_sizes, int n_in,
                              void* d_out, int out_size) {
    const float* x   = (const float*)d_in[0];
    const int*   ei  = (const int*)d_in[1];
    const int*   src = ei;
    const int*   dst = ei + Ed;
    const float* Wl0 = (const float*)d_in[2];
    const float* bl0 = (const float*)d_in[3];
    const float* Wr0 = (const float*)d_in[4];
    const float* Wl1 = (const float*)d_in[5];
    const float* bl1 = (const float*)d_in[6];
    const float* Wr1 = (const float*)d_in[7];
    const float* Wl2 = (const float*)d_in[8];
    const float* bl2 = (const float*)d_in[9];
    const float* Wr2 = (const float*)d_in[10];
    float* out = (float*)d_out;

    __half *yA, *yB;
    float *pA, *pB, *h0p, *h1p;
    cudaGetSymbolAddress((void**)&yA,  g_yA);
    cudaGetSymbolAddress((void**)&pA,  g_pA);
    cudaGetSymbolAddress((void**)&yB,  g_yB);
    cudaGetSymbolAddress((void**)&pB,  g_pB);
    cudaGetSymbolAddress((void**)&h0p, g_h0);
    cudaGetSymbolAddress((void**)&h1p, g_h1);

    const int ngrid  = (Nn + 255) / 256;
    const int e4grid = (Ed / 4 + 255) / 256;
    const int gAgrid = (NH * 32 + 255) / 256;
    const int gBgrid = ((Nn - NH) * 32 + 255) / 256;
    const int gFgrid = (Nn * 32 + 255) / 256;

    const int smem64 = (8 * 8 * 32 * 4) * 4 + 2 * 128 * 68 * 4 + 64 * 4;
    const int smem40 = (8 * 5 * 32 * 4) * 4 + 2 * 128 * 68 * 4 + 40 * 4;
    cudaFuncSetAttribute(transform_mma<64>,
                         cudaFuncAttributeMaxDynamicSharedMemorySize, smem64);
    cudaFuncSetAttribute(transform_mma<40>,
                         cudaFuncAttributeMaxDynamicSharedMemorySize, smem40);

    const int tgrid = 296;

    static cudaStream_t s2 = nullptr;
    static cudaEvent_t evFork = nullptr, evJoin = nullptr;
    static cudaEvent_t eG0a = nullptr, eT1a = nullptr, eG1a = nullptr, eT2a = nullptr;
    if (s2 == nullptr) {
        cudaStreamCreateWithFlags(&s2, cudaStreamNonBlocking);
        cudaEventCreateWithFlags(&evFork, cudaEventDisableTiming);
        cudaEventCreateWithFlags(&evJoin, cudaEventDisableTiming);
        cudaEventCreateWithFlags(&eG0a, cudaEventDisableTiming);
        cudaEventCreateWithFlags(&eT1a, cudaEventDisableTiming);
        cudaEventCreateWithFlags(&eG1a, cudaEventDisableTiming);
        cudaEventCreateWithFlags(&eT2a, cudaEventDisableTiming);
    }

    // ---- Fork: T0 (x -> yA,pA) on s2 overlaps CSR build on s0 ----
    cudaEventRecord(evFork, 0);
    cudaStreamWaitEvent(s2, evFork, 0);
    transform_mma<64><<<tgrid, 256, smem64, s2>>>(x, Wl0, bl0, Wr0, yA, pA, 0, NTILES);
    cudaEventRecord(evJoin, s2);

    zero_deg_kernel<<<ngrid, 256>>>();
    deg_kernel<<<e4grid, 256>>>(dst);
    scanA_kernel<<<NB_SCAN, 1024>>>();
    scanC_kernel<<<ngrid, 256>>>();
    fill_kernel<<<e4grid, 256>>>(src, dst);
    cudaStreamWaitEvent(0, evJoin, 0);

    // ---- G0 split; T1a overlaps G0b ----
    gather_kernel<64, true, false><<<gAgrid, 256>>>(yA, pA, h0p, 0, NH);
    cudaEventRecord(eG0a, 0);
    gather_kernel<64, true, false><<<gBgrid, 256>>>(yA, pA, h0p, NH, Nn);

    cudaStreamWaitEvent(s2, eG0a, 0);
    transform_mma<64><<<tgrid, 256, smem64, s2>>>(h0p, Wl1, bl1, Wr1, yB, pB, 0, TILES_A);
    cudaEventRecord(eT1a, s2);
    transform_mma<64><<<tgrid, 256, smem64>>>(h0p, Wl1, bl1, Wr1, yB, pB, TILES_A, NTILES);
    cudaStreamWaitEvent(0, eT1a, 0);

    // ---- G1 split; T2a overlaps G1b ----
    gather_kernel<64, true, false><<<gAgrid, 256>>>(yB, pB, h1p, 0, NH);
    cudaEventRecord(eG1a, 0);
    gather_kernel<64, true, false><<<gBgrid, 256>>>(yB, pB, h1p, NH, Nn);

    cudaStreamWaitEvent(s2, eG1a, 0);
    transform_mma<40><<<tgrid, 256, smem40, s2>>>(h1p, Wl2, bl2, Wr2, yA, pA, 0, TILES_A);
    cudaEventRecord(eT2a, s2);
    transform_mma<40><<<tgrid, 256, smem40>>>(h1p, Wl2, bl2, Wr2, yA, pA, TILES_A, NTILES);
    cudaStreamWaitEvent(0, eT2a, 0);

    // ---- Final gather + fused log_softmax ----
    gather_kernel<40, false, true><<<gFgrid, 256>>>(yA, pA, out, 0, Nn);
}

// round 10
// speedup vs baseline: 1.0181x; 1.0181x over previous
#include <cuda_runtime.h>
#include <cuda_fp16.h>
#include <math.h>
#include <stdint.h>

constexpr int Nn = 100000;
constexpr int Ed = 1600000;
constexpr int DIN = 64;
constexpr int NB_SCAN = (Nn + 1023) / 1024;   // 98
constexpr int NTILES  = (Nn + 127) / 128;     // 782
constexpr int CSR_CAP = Ed + 4 * Nn;          // aligned-row padding

// ---- scratch (device globals; no allocation allowed) ----------------------
__device__ __half g_y[(size_t)Nn * 64];
__device__ float  g_p[(size_t)Nn * 64];
__device__ float  g_h0[(size_t)Nn * 64];
__device__ float  g_h1[(size_t)Nn * 64];
__device__ int    g_csr_src[CSR_CAP];
__device__ int    g_rowptr[Nn];               // 4-aligned row starts
__device__ int    g_rowloc[Nn];
__device__ int    g_cursor[Nn];
__device__ int    g_deg[Nn];                  // true degree
__device__ float  g_invdeg[Nn];
__device__ int    g_bsum[NB_SCAN];

// ---------------------------------------------------------------------------
__global__ void zero_deg_kernel() {
    int i = blockIdx.x * blockDim.x + threadIdx.x;
    if (i < Nn) g_deg[i] = 0;
}

__global__ void deg_kernel(const int* __restrict__ dst) {
    int e4 = blockIdx.x * blockDim.x + threadIdx.x;
    if (e4 < Ed / 4) {
        int4 d = __ldg(reinterpret_cast<const int4*>(dst) + e4);
        atomicAdd(&g_deg[d.x], 1);
        atomicAdd(&g_deg[d.y], 1);
        atomicAdd(&g_deg[d.z], 1);
        atomicAdd(&g_deg[d.w], 1);
    }
}

// warp-shuffle block scan over ALIGNED degrees ((deg+3)&~3); invdeg fused.
__global__ void scanA_kernel() {
    __shared__ int wsum[32];
    int tid = threadIdx.x;
    int i = blockIdx.x * 1024 + tid;
    int v = (i < Nn) ? g_deg[i] : 0;
    if (i < Nn) g_invdeg[i] = 1.0f / fmaxf((float)v, 1.0f);
    int va = (v + 3) & ~3;                      // aligned degree
    int lane = tid & 31, wid = tid >> 5;
    int x = va;
#pragma unroll
    for (int o = 1; o < 32; o <<= 1) {
        int t = __shfl_up_sync(0xFFFFFFFFu, x, o);
        if (lane >= o) x += t;
    }
    if (lane == 31) wsum[wid] = x;
    __syncthreads();
    if (wid == 0) {
        int s = wsum[lane];
#pragma unroll
        for (int o = 1; o < 32; o <<= 1) {
            int t = __shfl_up_sync(0xFFFFFFFFu, s, o);
            if (lane >= o) s += t;
        }
        wsum[lane] = s;
    }
    __syncthreads();
    int incl = x + ((wid > 0) ? wsum[wid - 1] : 0);
    if (i < Nn) g_rowloc[i] = incl - va;
    if (tid == 1023) g_bsum[blockIdx.x] = incl;
}

__global__ void scanC_kernel() {
    __shared__ int sb[NB_SCAN];
    int tid = threadIdx.x;
    for (int j = tid; j < NB_SCAN; j += 256) sb[j] = g_bsum[j];
    __syncthreads();
    int i = blockIdx.x * 256 + tid;
    if (i < Nn) {
        int blk = i >> 10;
        int off = 0;
        for (int j = 0; j < blk; j++) off += sb[j];
        int r = g_rowloc[i] + off;
        g_rowptr[i] = r;
        g_cursor[i] = r;
    }
}

__global__ void fill_kernel(const int* __restrict__ src,
                            const int* __restrict__ dst) {
    int e4 = blockIdx.x * blockDim.x + threadIdx.x;
    if (e4 < Ed / 4) {
        int4 s = __ldg(reinterpret_cast<const int4*>(src) + e4);
        int4 d = __ldg(reinterpret_cast<const int4*>(dst) + e4);
        g_csr_src[atomicAdd(&g_cursor[d.x], 1)] = s.x;
        g_csr_src[atomicAdd(&g_cursor[d.y], 1)] = s.y;
        g_csr_src[atomicAdd(&g_cursor[d.z], 1)] = s.z;
        g_csr_src[atomicAdd(&g_cursor[d.w], 1)] = s.w;
    }
}

// ---------------------------------------------------------------------------
__device__ __forceinline__ uint32_t f2tf32(float x) {
    uint32_t r;
    asm("cvt.rna.tf32.f32 %0, %1;" : "=r"(r) : "f"(x));
    return r;
}

__device__ __forceinline__ void mma_tf32(float c[4], const uint32_t a[4],
                                         const uint32_t b0, const uint32_t b1) {
    asm volatile(
        "mma.sync.aligned.m16n8k8.row.col.f32.tf32.tf32.f32 "
        "{%0,%1,%2,%3}, {%4,%5,%6,%7}, {%8,%9}, {%0,%1,%2,%3};"
        : "+f"(c[0]), "+f"(c[1]), "+f"(c[2]), "+f"(c[3])
        : "r"(a[0]), "r"(a[1]), "r"(a[2]), "r"(a[3]), "r"(b0), "r"(b1));
}

__device__ __forceinline__ uint32_t s2u(const void* p) {
    uint32_t a;
    asm("{.reg .u64 t; cvta.to.shared.u64 t, %1; cvt.u32.u64 %0, t;}"
        : "=r"(a) : "l"(p));
    return a;
}

__device__ __forceinline__ void cp16(uint32_t dst, const void* src) {
    asm volatile("cp.async.cg.shared.global [%0], [%1], 16;"
                 :: "r"(dst), "l"(src));
}

// ---------------------------------------------------------------------------
// Transform via tf32 tensor cores (fragment-ordered W, cp.async H pipeline).
// ---------------------------------------------------------------------------
template <int DOUT>
__global__ void transform_mma(const float* __restrict__ hin,
                              const float* __restrict__ Wl,
                              const float* __restrict__ bl,
                              const float* __restrict__ Wr,
                              __half* __restrict__ y,
                              float* __restrict__ p) {
    constexpr int NC  = 2 * DOUT;
    constexpr int NT  = NC / 8;
    constexpr int NQ  = NT / 2;
    constexpr int SHP = 68;
    constexpr int WF_WORDS = 8 * NQ * 32 * 4;

    extern __shared__ uint32_t smem[];
    uint32_t* sWf = smem;
    float* sHA = (float*)(smem + WF_WORDS);
    float* sHB = sHA + 128 * SHP;
    float* sbl = sHB + 128 * SHP;

    const int tid = threadIdx.x;
    const int w   = tid >> 5;
    const int l   = tid & 31;
    const int g   = l >> 2;
    const int tig = l & 3;

    for (int idx = tid; idx < 8 * NQ * 32; idx += 256) {
        int ks  = idx / (NQ * 32);
        int rem = idx - ks * (NQ * 32);
        int q   = rem >> 5;
        int ll  = rem & 31;
        int gg  = ll >> 2;
        int tt  = ll & 3;
        int k_lo = ks * 8 + tt;
        int k_hi = k_lo + 4;
        uint4 frag;
        {
            int cc = (2 * q) * 8 + gg;
            const float* basev = (cc < DOUT) ? (Wl + cc) : (Wr + cc - DOUT);
            frag.x = f2tf32(__ldg(basev + k_lo * DOUT));
            frag.y = f2tf32(__ldg(basev + k_hi * DOUT));
        }
        {
            int cc = (2 * q + 1) * 8 + gg;
            const float* basev = (cc < DOUT) ? (Wl + cc) : (Wr + cc - DOUT);
            frag.z = f2tf32(__ldg(basev + k_lo * DOUT));
            frag.w = f2tf32(__ldg(basev + k_hi * DOUT));
        }
        reinterpret_cast<uint4*>(sWf)[idx] = frag;
    }
    if (tid < DOUT) sbl[tid] = bl[tid];

    const uint4* wf = reinterpret_cast<const uint4*>(sWf) + l;

    auto stage = [&](int tile, float* buf) {
        if (tile < NTILES) {
            const int base = tile * 128;
            const uint32_t bufu = s2u(buf);
            for (int v = tid; v < 2048; v += 256) {
                int r  = v >> 4;
                int cb = (v & 15) * 16;
                int node = base + r;
                uint32_t d = bufu + (uint32_t)(r * (SHP * 4) + cb);
                if (node < Nn)
                    cp16(d, (const char*)(hin + (size_t)node * 64) + cb);
                else
                    *reinterpret_cast<float4*>((char*)buf + r * (SHP * 4) + cb) =
                        make_float4(0.f, 0.f, 0.f, 0.f);
            }
        }
        asm volatile("cp.async.commit_group;");
    };

    float* cur = sHA;
    float* nxt = sHB;
    int tile = blockIdx.x;
    stage(tile, cur);

    for (; tile < NTILES; tile += gridDim.x) {
        stage(tile + gridDim.x, nxt);
        asm volatile("cp.async.wait_group 1;");
        __syncthreads();

        float c[NT][4];
#pragma unroll
        for (int nt = 0; nt < NT; nt++) {
            c[nt][0] = 0.f; c[nt][1] = 0.f; c[nt][2] = 0.f; c[nt][3] = 0.f;
        }

        const float* sHr0 = cur + (16 * w + g) * SHP;
        const float* sHr1 = sHr0 + 8 * SHP;

#pragma unroll
        for (int ks = 0; ks < 8; ks++) {
            const int k0 = ks * 8;
            uint32_t a[4];
            a[0] = f2tf32(sHr0[k0 + tig]);
            a[1] = f2tf32(sHr1[k0 + tig]);
            a[2] = f2tf32(sHr0[k0 + tig + 4]);
            a[3] = f2tf32(sHr1[k0 + tig + 4]);
#pragma unroll
            for (int q = 0; q < NQ; q++) {
                uint4 b = wf[(ks * NQ + q) * 32];
                mma_tf32(c[2 * q],     a, b.x, b.y);
                mma_tf32(c[2 * q + 1], a, b.z, b.w);
            }
        }

        const int base = tile * 128;
        const int node0 = base + 16 * w + g;
        const int node1 = node0 + 8;
#pragma unroll
        for (int nt = 0; nt < NT; nt++) {
            int col = nt * 8 + 2 * tig;
            if (col < DOUT) {
                if (node0 < Nn)
                    *reinterpret_cast<__half2*>(y + (size_t)node0 * DOUT + col) =
                        __floats2half2_rn(c[nt][0], c[nt][1]);
                if (node1 < Nn)
                    *reinterpret_cast<__half2*>(y + (size_t)node1 * DOUT + col) =
                        __floats2half2_rn(c[nt][2], c[nt][3]);
            } else {
                int pc = col - DOUT;
                float b0 = sbl[pc], b1 = sbl[pc + 1];
                if (node0 < Nn)
                    *reinterpret_cast<float2*>(p + (size_t)node0 * DOUT + pc) =
                        make_float2(c[nt][0] + b0, c[nt][1] + b1);
                if (node1 < Nn)
                    *reinterpret_cast<float2*>(p + (size_t)node1 * DOUT + pc) =
                        make_float2(c[nt][2] + b0, c[nt][3] + b1);
            }
        }
        __syncthreads();
        float* t = cur; cur = nxt; nxt = t;
    }
}

// ---------------------------------------------------------------------------
// Gather: warp per node. Indices loaded as two int4 per 8 neighbors
// (CSR rows are 16B-aligned), rows as half2 per lane.
// ---------------------------------------------------------------------------
template <int DOUT, bool RELU, bool FINAL>
__global__ void gather_kernel(const __half* __restrict__ y,
                              const float* __restrict__ p,
                              float* __restrict__ out) {
    int w = (blockIdx.x * blockDim.x + threadIdx.x) >> 5;
    int lane = threadIdx.x & 31;
    if (w >= Nn) return;
    const bool act = (2 * lane) < DOUT;

    const int start = g_rowptr[w];          // multiple of 4
    const int cnt   = g_deg[w];
    const int* __restrict__ idxp = g_csr_src + start;
    const __half2* __restrict__ y2 = reinterpret_cast<const __half2*>(y);
    constexpr int STRIDE = DOUT / 2;

    float2 acc = make_float2(0.f, 0.f);
    int i = 0;
    for (; i + 8 <= cnt; i += 8) {
        int4 ia = __ldg(reinterpret_cast<const int4*>(idxp + i));
        int4 ib = __ldg(reinterpret_cast<const int4*>(idxp + i + 4));
        if (act) {
            __half2 v0 = __ldg(y2 + (size_t)ia.x * STRIDE + lane);
            __half2 v1 = __ldg(y2 + (size_t)ia.y * STRIDE + lane);
            __half2 v2 = __ldg(y2 + (size_t)ia.z * STRIDE + lane);
            __half2 v3 = __ldg(y2 + (size_t)ia.w * STRIDE + lane);
            __half2 v4 = __ldg(y2 + (size_t)ib.x * STRIDE + lane);
            __half2 v5 = __ldg(y2 + (size_t)ib.y * STRIDE + lane);
            __half2 v6 = __ldg(y2 + (size_t)ib.z * STRIDE + lane);
            __half2 v7 = __ldg(y2 + (size_t)ib.w * STRIDE + lane);
            float2 f0 = __half22float2(v0), f1 = __half22float2(v1);
            float2 f2 = __half22float2(v2), f3 = __half22float2(v3);
            float2 f4 = __half22float2(v4), f5 = __half22float2(v5);
            float2 f6 = __half22float2(v6), f7 = __half22float2(v7);
            acc.x += ((f0.x + f1.x) + (f2.x + f3.x)) + ((f4.x + f5.x) + (f6.x + f7.x));
            acc.y += ((f0.y + f1.y) + (f2.y + f3.y)) + ((f4.y + f5.y) + (f6.y + f7.y));
        }
    }
    if (i < cnt) {                              // tail: one aligned int4 covers up to 4
        for (; i < cnt; i += 4) {
            int4 ia = __ldg(reinterpret_cast<const int4*>(idxp + i));
            int rem = cnt - i;
            if (act) {
                float2 f;
                f = __half22float2(__ldg(y2 + (size_t)ia.x * STRIDE + lane));
                acc.x += f.x; acc.y += f.y;
                if (rem > 1) {
                    f = __half22float2(__ldg(y2 + (size_t)ia.y * STRIDE + lane));
                    acc.x += f.x; acc.y += f.y;
                }
                if (rem > 2) {
                    f = __half22float2(__ldg(y2 + (size_t)ia.z * STRIDE + lane));
                    acc.x += f.x; acc.y += f.y;
                }
                if (rem > 3) {
                    f = __half22float2(__ldg(y2 + (size_t)ia.w * STRIDE + lane));
                    acc.x += f.x; acc.y += f.y;
                }
            }
        }
    }

    float invd = g_invdeg[w];
    float2 o = make_float2(0.f, 0.f);
    if (act) {
        float2 pp = *reinterpret_cast<const float2*>(p + (size_t)w * DOUT + 2 * lane);
        o.x = fmaf(acc.x, invd, pp.x);
        o.y = fmaf(acc.y, invd, pp.y);
        if (RELU) { o.x = fmaxf(o.x, 0.f); o.y = fmaxf(o.y, 0.f); }
    }

    if (FINAL) {
        float m = act ? fmaxf(o.x, o.y) : -INFINITY;
#pragma unroll
        for (int off = 16; off; off >>= 1) m = fmaxf(m, __shfl_xor_sync(0xFFFFFFFFu, m, off));
        float s = act ? (expf(o.x - m) + expf(o.y - m)) : 0.f;
#pragma unroll
        for (int off = 16; off; off >>= 1) s += __shfl_xor_sync(0xFFFFFFFFu, s, off);
        float lse = m + logf(s);
        o.x -= lse;
        o.y -= lse;
    }
    if (act)
        *reinterpret_cast<float2*>(out + (size_t)w * DOUT + 2 * lane) = o;
}

// ---------------------------------------------------------------------------
extern "C" void kernel_launch(void* const* d_in, const int* in_sizes, int n_in,
                              void* d_out, int out_size) {
    const float* x   = (const float*)d_in[0];
    const int*   ei  = (const int*)d_in[1];
    const int*   src = ei;
    const int*   dst = ei + Ed;
    const float* Wl0 = (const float*)d_in[2];
    const float* bl0 = (const float*)d_in[3];
    const float* Wr0 = (const float*)d_in[4];
    const float* Wl1 = (const float*)d_in[5];
    const float* bl1 = (const float*)d_in[6];
    const float* Wr1 = (const float*)d_in[7];
    const float* Wl2 = (const float*)d_in[8];
    const float* bl2 = (const float*)d_in[9];
    const float* Wr2 = (const float*)d_in[10];
    float* out = (float*)d_out;

    __half* yp;
    float *pp, *h0p, *h1p;
    cudaGetSymbolAddress((void**)&yp,  g_y);
    cudaGetSymbolAddress((void**)&pp,  g_p);
    cudaGetSymbolAddress((void**)&h0p, g_h0);
    cudaGetSymbolAddress((void**)&h1p, g_h1);

    const int ngrid  = (Nn + 255) / 256;
    const int e4grid = (Ed / 4 + 255) / 256;
    const int ggrid  = (Nn * 32 + 255) / 256;

    const int smem64 = (8 * 8 * 32 * 4) * 4 + 2 * 128 * 68 * 4 + 64 * 4;
    const int smem40 = (8 * 5 * 32 * 4) * 4 + 2 * 128 * 68 * 4 + 40 * 4;
    cudaFuncSetAttribute(transform_mma<64>,
                         cudaFuncAttributeMaxDynamicSharedMemorySize, smem64);
    cudaFuncSetAttribute(transform_mma<40>,
                         cudaFuncAttributeMaxDynamicSharedMemorySize, smem40);

    const int tgrid = 296;

    static cudaStream_t s2 = nullptr;
    static cudaEvent_t evFork = nullptr, evJoin = nullptr;
    if (s2 == nullptr) {
        cudaStreamCreateWithFlags(&s2, cudaStreamNonBlocking);
        cudaEventCreateWithFlags(&evFork, cudaEventDisableTiming);
        cudaEventCreateWithFlags(&evJoin, cudaEventDisableTiming);
    }

    // ---- Fork: T0 on s2 overlaps CSR build on stream 0 (R7 schedule) ----
    cudaEventRecord(evFork, 0);
    cudaStreamWaitEvent(s2, evFork, 0);
    transform_mma<64><<<tgrid, 256, smem64, s2>>>(x, Wl0, bl0, Wr0, yp, pp);
    cudaEventRecord(evJoin, s2);

    zero_deg_kernel<<<ngrid, 256>>>();
    deg_kernel<<<e4grid, 256>>>(dst);
    scanA_kernel<<<NB_SCAN, 1024>>>();
    scanC_kernel<<<ngrid, 256>>>();
    fill_kernel<<<e4grid, 256>>>(src, dst);
    cudaStreamWaitEvent(0, evJoin, 0);

    // ---- Layer 0 gather ----
    gather_kernel<64, true, false><<<ggrid, 256>>>(yp, pp, h0p);

    // ---- Layer 1 ----
    transform_mma<64><<<tgrid, 256, smem64>>>(h0p, Wl1, bl1, Wr1, yp, pp);
    gather_kernel<64, true, false><<<ggrid, 256>>>(yp, pp, h1p);

    // ---- Layer 2 (gather fused with log_softmax) ----
    transform_mma<40><<<tgrid, 256, smem40>>>(h1p, Wl2, bl2, Wr2, yp, pp);
    gather_kernel<40, false, true><<<ggrid, 256>>>(yp, pp, out);
}

// round 11
// speedup vs baseline: 1.0939x; 1.0744x over previous
#include <cuda_runtime.h>
#include <cuda_fp16.h>
#include <math.h>
#include <stdint.h>

constexpr int Nn = 100000;
constexpr int Ed = 1600000;
constexpr int DIN = 64;
constexpr int NB_SCAN = (Nn + 1023) / 1024;   // 98
constexpr int NTILES  = (Nn + 127) / 128;     // 782

// ---- scratch (device globals; no allocation allowed) ----------------------
__device__ __half g_y[(size_t)Nn * 64];       // h @ Wl           (fp16)
__device__ __half g_p[(size_t)Nn * 64];       // h @ Wr + bl      (fp16)
__device__ __half g_h0[(size_t)Nn * 64];      // layer outputs    (fp16)
__device__ __half g_h1[(size_t)Nn * 64];
__device__ int    g_csr_src[Ed];
__device__ int    g_rowptr[Nn];
__device__ int    g_rowloc[Nn];
__device__ int    g_cursor[Nn];
__device__ int    g_deg[Nn];
__device__ float  g_invdeg[Nn];
__device__ int    g_bsum[NB_SCAN];

// ---------------------------------------------------------------------------
__global__ void zero_deg_kernel() {
    int i = blockIdx.x * blockDim.x + threadIdx.x;
    if (i < Nn) g_deg[i] = 0;
}

__global__ void deg_kernel(const int* __restrict__ dst) {
    int e4 = blockIdx.x * blockDim.x + threadIdx.x;
    if (e4 < Ed / 4) {
        int4 d = __ldg(reinterpret_cast<const int4*>(dst) + e4);
        atomicAdd(&g_deg[d.x], 1);
        atomicAdd(&g_deg[d.y], 1);
        atomicAdd(&g_deg[d.z], 1);
        atomicAdd(&g_deg[d.w], 1);
    }
}

// warp-shuffle block scan; invdeg fused
__global__ void scanA_kernel() {
    __shared__ int wsum[32];
    int tid = threadIdx.x;
    int i = blockIdx.x * 1024 + tid;
    int v = (i < Nn) ? g_deg[i] : 0;
    if (i < Nn) g_invdeg[i] = 1.0f / fmaxf((float)v, 1.0f);
    int lane = tid & 31, wid = tid >> 5;
    int x = v;
#pragma unroll
    for (int o = 1; o < 32; o <<= 1) {
        int t = __shfl_up_sync(0xFFFFFFFFu, x, o);
        if (lane >= o) x += t;
    }
    if (lane == 31) wsum[wid] = x;
    __syncthreads();
    if (wid == 0) {
        int s = wsum[lane];
#pragma unroll
        for (int o = 1; o < 32; o <<= 1) {
            int t = __shfl_up_sync(0xFFFFFFFFu, s, o);
            if (lane >= o) s += t;
        }
        wsum[lane] = s;
    }
    __syncthreads();
    int incl = x + ((wid > 0) ? wsum[wid - 1] : 0);
    if (i < Nn) g_rowloc[i] = incl - v;
    if (tid == 1023) g_bsum[blockIdx.x] = incl;
}

__global__ void scanC_kernel() {
    __shared__ int sb[NB_SCAN];
    int tid = threadIdx.x;
    for (int j = tid; j < NB_SCAN; j += 256) sb[j] = g_bsum[j];
    __syncthreads();
    int i = blockIdx.x * 256 + tid;
    if (i < Nn) {
        int blk = i >> 10;
        int off = 0;
        for (int j = 0; j < blk; j++) off += sb[j];
        int r = g_rowloc[i] + off;
        g_rowptr[i] = r;
        g_cursor[i] = r;
    }
}

__global__ void fill_kernel(const int* __restrict__ src,
                            const int* __restrict__ dst) {
    int e4 = blockIdx.x * blockDim.x + threadIdx.x;
    if (e4 < Ed / 4) {
        int4 s = __ldg(reinterpret_cast<const int4*>(src) + e4);
        int4 d = __ldg(reinterpret_cast<const int4*>(dst) + e4);
        g_csr_src[atomicAdd(&g_cursor[d.x], 1)] = s.x;
        g_csr_src[atomicAdd(&g_cursor[d.y], 1)] = s.y;
        g_csr_src[atomicAdd(&g_cursor[d.z], 1)] = s.z;
        g_csr_src[atomicAdd(&g_cursor[d.w], 1)] = s.w;
    }
}

// ---------------------------------------------------------------------------
__device__ __forceinline__ uint32_t f2tf32(float x) {
    uint32_t r;
    asm("cvt.rna.tf32.f32 %0, %1;" : "=r"(r) : "f"(x));
    return r;
}

__device__ __forceinline__ void mma_tf32(float c[4], const uint32_t a[4],
                                         const uint32_t b0, const uint32_t b1) {
    asm volatile(
        "mma.sync.aligned.m16n8k8.row.col.f32.tf32.tf32.f32 "
        "{%0,%1,%2,%3}, {%4,%5,%6,%7}, {%8,%9}, {%0,%1,%2,%3};"
        : "+f"(c[0]), "+f"(c[1]), "+f"(c[2]), "+f"(c[3])
        : "r"(a[0]), "r"(a[1]), "r"(a[2]), "r"(a[3]), "r"(b0), "r"(b1));
}

__device__ __forceinline__ uint32_t s2u(const void* p) {
    uint32_t a;
    asm("{.reg .u64 t; cvta.to.shared.u64 t, %1; cvt.u32.u64 %0, t;}"
        : "=r"(a) : "l"(p));
    return a;
}

__device__ __forceinline__ void cp16(uint32_t dst, const void* src) {
    asm volatile("cp.async.cg.shared.global [%0], [%1], 16;"
                 :: "r"(dst), "l"(src));
}

// ---------------------------------------------------------------------------
// Transform via tf32 tensor cores; input TIN in {float, __half}.
// C[128 x 2*DOUT] = H[128 x 64] @ [Wl | Wr]; y (fp16), p (fp16, +bl).
// ---------------------------------------------------------------------------
template <int DOUT, typename TIN>
__global__ void transform_mma(const TIN* __restrict__ hin,
                              const float* __restrict__ Wl,
                              const float* __restrict__ bl,
                              const float* __restrict__ Wr,
                              __half* __restrict__ y,
                              __half* __restrict__ p) {
    constexpr bool IN_HALF = (sizeof(TIN) == 2);
    constexpr int NC  = 2 * DOUT;
    constexpr int NT  = NC / 8;
    constexpr int NQ  = NT / 2;
    constexpr int SHPB   = IN_HALF ? 144 : 272;      // padded row stride, bytes
    constexpr int CHUNKS = IN_HALF ? 8 : 16;         // 16B chunks per row
    constexpr int WF_WORDS = 8 * NQ * 32 * 4;

    extern __shared__ uint32_t smem[];
    uint32_t* sWf = smem;
    char* sHA = (char*)(smem + WF_WORDS);
    char* sHB = sHA + 128 * SHPB;
    float* sbl = (float*)(sHB + 128 * SHPB);

    const int tid = threadIdx.x;
    const int w   = tid >> 5;
    const int l   = tid & 31;
    const int g   = l >> 2;
    const int tig = l & 3;

    for (int idx = tid; idx < 8 * NQ * 32; idx += 256) {
        int ks  = idx / (NQ * 32);
        int rem = idx - ks * (NQ * 32);
        int q   = rem >> 5;
        int ll  = rem & 31;
        int gg  = ll >> 2;
        int tt  = ll & 3;
        int k_lo = ks * 8 + tt;
        int k_hi = k_lo + 4;
        uint4 frag;
        {
            int cc = (2 * q) * 8 + gg;
            const float* basev = (cc < DOUT) ? (Wl + cc) : (Wr + cc - DOUT);
            frag.x = f2tf32(__ldg(basev + k_lo * DOUT));
            frag.y = f2tf32(__ldg(basev + k_hi * DOUT));
        }
        {
            int cc = (2 * q + 1) * 8 + gg;
            const float* basev = (cc < DOUT) ? (Wl + cc) : (Wr + cc - DOUT);
            frag.z = f2tf32(__ldg(basev + k_lo * DOUT));
            frag.w = f2tf32(__ldg(basev + k_hi * DOUT));
        }
        reinterpret_cast<uint4*>(sWf)[idx] = frag;
    }
    if (tid < DOUT) sbl[tid] = bl[tid];

    const uint4* wf = reinterpret_cast<const uint4*>(sWf) + l;

    auto stage = [&](int tile, char* buf) {
        if (tile < NTILES) {
            const int base = tile * 128;
            const uint32_t bufu = s2u(buf);
            for (int v = tid; v < 128 * CHUNKS; v += 256) {
                int r  = v / CHUNKS;
                int cb = (v - r * CHUNKS) * 16;
                int node = base + r;
                uint32_t d = bufu + (uint32_t)(r * SHPB + cb);
                if (node < Nn)
                    cp16(d, (const char*)(hin + (size_t)node * 64) + cb);
                else
                    *reinterpret_cast<uint4*>(buf + r * SHPB + cb) =
                        make_uint4(0, 0, 0, 0);
            }
        }
        asm volatile("cp.async.commit_group;");
    };

    char* cur = sHA;
    char* nxt = sHB;
    int tile = blockIdx.x;
    stage(tile, cur);

    for (; tile < NTILES; tile += gridDim.x) {
        stage(tile + gridDim.x, nxt);
        asm volatile("cp.async.wait_group 1;");
        __syncthreads();

        float c[NT][4];
#pragma unroll
        for (int nt = 0; nt < NT; nt++) {
            c[nt][0] = 0.f; c[nt][1] = 0.f; c[nt][2] = 0.f; c[nt][3] = 0.f;
        }

        const char* rp0 = cur + (16 * w + g) * SHPB;
        const char* rp1 = rp0 + 8 * SHPB;

#pragma unroll
        for (int ks = 0; ks < 8; ks++) {
            const int k0 = ks * 8;
            uint32_t a[4];
            if (IN_HALF) {
                const __half* h0r = (const __half*)rp0;
                const __half* h1r = (const __half*)rp1;
                a[0] = f2tf32(__half2float(h0r[k0 + tig]));
                a[1] = f2tf32(__half2float(h1r[k0 + tig]));
                a[2] = f2tf32(__half2float(h0r[k0 + tig + 4]));
                a[3] = f2tf32(__half2float(h1r[k0 + tig + 4]));
            } else {
                const float* f0r = (const float*)rp0;
                const float* f1r = (const float*)rp1;
                a[0] = f2tf32(f0r[k0 + tig]);
                a[1] = f2tf32(f1r[k0 + tig]);
                a[2] = f2tf32(f0r[k0 + tig + 4]);
                a[3] = f2tf32(f1r[k0 + tig + 4]);
            }
#pragma unroll
            for (int q = 0; q < NQ; q++) {
                uint4 b = wf[(ks * NQ + q) * 32];
                mma_tf32(c[2 * q],     a, b.x, b.y);
                mma_tf32(c[2 * q + 1], a, b.z, b.w);
            }
        }

        const int base = tile * 128;
        const int node0 = base + 16 * w + g;
        const int node1 = node0 + 8;
#pragma unroll
        for (int nt = 0; nt < NT; nt++) {
            int col = nt * 8 + 2 * tig;
            if (col < DOUT) {
                if (node0 < Nn)
                    *reinterpret_cast<__half2*>(y + (size_t)node0 * DOUT + col) =
                        __floats2half2_rn(c[nt][0], c[nt][1]);
                if (node1 < Nn)
                    *reinterpret_cast<__half2*>(y + (size_t)node1 * DOUT + col) =
                        __floats2half2_rn(c[nt][2], c[nt][3]);
            } else {
                int pc = col - DOUT;
                float b0 = sbl[pc], b1 = sbl[pc + 1];
                if (node0 < Nn)
                    *reinterpret_cast<__half2*>(p + (size_t)node0 * DOUT + pc) =
                        __floats2half2_rn(c[nt][0] + b0, c[nt][1] + b1);
                if (node1 < Nn)
                    *reinterpret_cast<__half2*>(p + (size_t)node1 * DOUT + pc) =
                        __floats2half2_rn(c[nt][2] + b0, c[nt][3] + b1);
            }
        }
        __syncthreads();
        char* t = cur; cur = nxt; nxt = t;
    }
}

// ---------------------------------------------------------------------------
// Gather: out[n] = act( invdeg[n] * sum_{j in N(n)} y[j] + p[n] )
// Warp per node; scalar broadcast index loads (R7 best config), x8 unroll.
// FINAL: fp32 out + fused log_softmax; else fp16 out.
// ---------------------------------------------------------------------------
template <int DOUT, bool RELU, bool FINAL>
__global__ void gather_kernel(const __half* __restrict__ y,
                              const __half* __restrict__ p,
                              void* __restrict__ outv) {
    int w = (blockIdx.x * blockDim.x + threadIdx.x) >> 5;
    int lane = threadIdx.x & 31;
    if (w >= Nn) return;
    const bool act = (2 * lane) < DOUT;

    const int start = g_rowptr[w];
    const int cnt   = g_deg[w];
    const int* __restrict__ idxp = g_csr_src + start;
    const __half2* __restrict__ y2 = reinterpret_cast<const __half2*>(y);
    constexpr int STRIDE = DOUT / 2;

    float2 acc = make_float2(0.f, 0.f);
    int i = 0;
    for (; i + 8 <= cnt; i += 8) {
        int s0 = __ldg(idxp + i + 0);
        int s1 = __ldg(idxp + i + 1);
        int s2 = __ldg(idxp + i + 2);
        int s3 = __ldg(idxp + i + 3);
        int s4 = __ldg(idxp + i + 4);
        int s5 = __ldg(idxp + i + 5);
        int s6 = __ldg(idxp + i + 6);
        int s7 = __ldg(idxp + i + 7);
        if (act) {
            __half2 v0 = __ldg(y2 + (size_t)s0 * STRIDE + lane);
            __half2 v1 = __ldg(y2 + (size_t)s1 * STRIDE + lane);
            __half2 v2 = __ldg(y2 + (size_t)s2 * STRIDE + lane);
            __half2 v3 = __ldg(y2 + (size_t)s3 * STRIDE + lane);
            __half2 v4 = __ldg(y2 + (size_t)s4 * STRIDE + lane);
            __half2 v5 = __ldg(y2 + (size_t)s5 * STRIDE + lane);
            __half2 v6 = __ldg(y2 + (size_t)s6 * STRIDE + lane);
            __half2 v7 = __ldg(y2 + (size_t)s7 * STRIDE + lane);
            float2 f0 = __half22float2(v0), f1 = __half22float2(v1);
            float2 f2 = __half22float2(v2), f3 = __half22float2(v3);
            float2 f4 = __half22float2(v4), f5 = __half22float2(v5);
            float2 f6 = __half22float2(v6), f7 = __half22float2(v7);
            acc.x += ((f0.x + f1.x) + (f2.x + f3.x)) + ((f4.x + f5.x) + (f6.x + f7.x));
            acc.y += ((f0.y + f1.y) + (f2.y + f3.y)) + ((f4.y + f5.y) + (f6.y + f7.y));
        }
    }
    for (; i < cnt; i++) {
        int s = __ldg(idxp + i);
        if (act) {
            float2 f = __half22float2(__ldg(y2 + (size_t)s * STRIDE + lane));
            acc.x += f.x;
            acc.y += f.y;
        }
    }

    float invd = g_invdeg[w];
    float2 o = make_float2(0.f, 0.f);
    if (act) {
        float2 pp = __half22float2(
            *reinterpret_cast<const __half2*>(p + (size_t)w * DOUT + 2 * lane));
        o.x = fmaf(acc.x, invd, pp.x);
        o.y = fmaf(acc.y, invd, pp.y);
        if (RELU) { o.x = fmaxf(o.x, 0.f); o.y = fmaxf(o.y, 0.f); }
    }

    if (FINAL) {
        float m = act ? fmaxf(o.x, o.y) : -INFINITY;
#pragma unroll
        for (int off = 16; off; off >>= 1) m = fmaxf(m, __shfl_xor_sync(0xFFFFFFFFu, m, off));
        float s = act ? (expf(o.x - m) + expf(o.y - m)) : 0.f;
#pragma unroll
        for (int off = 16; off; off >>= 1) s += __shfl_xor_sync(0xFFFFFFFFu, s, off);
        float lse = m + logf(s);
        o.x -= lse;
        o.y -= lse;
        if (act) {
            float* out = (float*)outv;
            *reinterpret_cast<float2*>(out + (size_t)w * DOUT + 2 * lane) = o;
        }
    } else {
        if (act) {
            __half* out = (__half*)outv;
            *reinterpret_cast<__half2*>(out + (size_t)w * DOUT + 2 * lane) =
                __floats2half2_rn(o.x, o.y);
        }
    }
}

// ---------------------------------------------------------------------------
extern "C" void kernel_launch(void* const* d_in, const int* in_sizes, int n_in,
                              void* d_out, int out_size) {
    const float* x   = (const float*)d_in[0];
    const int*   ei  = (const int*)d_in[1];
    const int*   src = ei;
    const int*   dst = ei + Ed;
    const float* Wl0 = (const float*)d_in[2];
    const float* bl0 = (const float*)d_in[3];
    const float* Wr0 = (const float*)d_in[4];
    const float* Wl1 = (const float*)d_in[5];
    const float* bl1 = (const float*)d_in[6];
    const float* Wr1 = (const float*)d_in[7];
    const float* Wl2 = (const float*)d_in[8];
    const float* bl2 = (const float*)d_in[9];
    const float* Wr2 = (const float*)d_in[10];

    __half *yp, *pp, *h0p, *h1p;
    cudaGetSymbolAddress((void**)&yp,  g_y);
    cudaGetSymbolAddress((void**)&pp,  g_p);
    cudaGetSymbolAddress((void**)&h0p, g_h0);
    cudaGetSymbolAddress((void**)&h1p, g_h1);

    const int ngrid  = (Nn + 255) / 256;
    const int e4grid = (Ed / 4 + 255) / 256;
    const int ggrid  = (Nn * 32 + 255) / 256;

    // smem: fragment W + 2 H buffers + bias
    const int smem64f = (8 * 8 * 32 * 4) * 4 + 2 * 128 * 272 + 64 * 4;  // 102,656
    const int smem64h = (8 * 8 * 32 * 4) * 4 + 2 * 128 * 144 + 64 * 4;  //  69,888
    const int smem40h = (8 * 5 * 32 * 4) * 4 + 2 * 128 * 144 + 40 * 4;  //  57,504
    cudaFuncSetAttribute((const void*)transform_mma<64, float>,
                         cudaFuncAttributeMaxDynamicSharedMemorySize, smem64f);
    cudaFuncSetAttribute((const void*)transform_mma<64, __half>,
                         cudaFuncAttributeMaxDynamicSharedMemorySize, smem64h);
    cudaFuncSetAttribute((const void*)transform_mma<40, __half>,
                         cudaFuncAttributeMaxDynamicSharedMemorySize, smem40h);

    const int tgrid = 296;

    static cudaStream_t s2 = nullptr;
    static cudaEvent_t evFork = nullptr, evJoin = nullptr;
    if (s2 == nullptr) {
        cudaStreamCreateWithFlags(&s2, cudaStreamNonBlocking);
        cudaEventCreateWithFlags(&evFork, cudaEventDisableTiming);
        cudaEventCreateWithFlags(&evJoin, cudaEventDisableTiming);
    }

    // ---- Fork: T0 on s2 overlaps CSR build on stream 0 ----
    cudaEventRecord(evFork, 0);
    cudaStreamWaitEvent(s2, evFork, 0);
    transform_mma<64, float><<<tgrid, 256, smem64f, s2>>>(x, Wl0, bl0, Wr0, yp, pp);
    cudaEventRecord(evJoin, s2);

    zero_deg_kernel<<<ngrid, 256>>>();
    deg_kernel<<<e4grid, 256>>>(dst);
    scanA_kernel<<<NB_SCAN, 1024>>>();
    scanC_kernel<<<ngrid, 256>>>();
    fill_kernel<<<e4grid, 256>>>(src, dst);
    cudaStreamWaitEvent(0, evJoin, 0);

    // ---- Layer 0 gather ----
    gather_kernel<64, true, false><<<ggrid, 256>>>(yp, pp, h0p);

    // ---- Layer 1 ----
    transform_mma<64, __half><<<tgrid, 256, smem64h>>>(h0p, Wl1, bl1, Wr1, yp, pp);
    gather_kernel<64, true, false><<<ggrid, 256>>>(yp, pp, h1p);

    // ---- Layer 2 (gather fused with log_softmax) ----
    transform_mma<40, __half><<<tgrid, 256, smem40h>>>(h1p, Wl2, bl2, Wr2, yp, pp);
    gather_kernel<40, false, true><<<ggrid, 256>>>(yp, pp, d_out);
}

// round 12
// speedup vs baseline: 1.1907x; 1.0885x over previous
#include <cuda_runtime.h>
#include <cuda_fp16.h>
#include <math.h>
#include <stdint.h>

constexpr int Nn = 100000;
constexpr int Ed = 1600000;
constexpr int DIN = 64;
constexpr int NB_SCAN = (Nn + 1023) / 1024;   // 98
constexpr int NTILES  = (Nn + 127) / 128;     // 782

// ---- scratch (device globals; no allocation allowed) ----------------------
__device__ __half g_y[(size_t)Nn * 64];       // h @ Wl           (fp16)
__device__ __half g_p[(size_t)Nn * 64];       // h @ Wr + bl      (fp16)
__device__ __half g_h0[(size_t)Nn * 64];      // layer outputs    (fp16)
__device__ __half g_h1[(size_t)Nn * 64];
__device__ int    g_csr_src[Ed];
__device__ int    g_rowptr[Nn];
__device__ int    g_rowloc[Nn];
__device__ int    g_cursor[Nn];
__device__ int    g_deg[Nn];
__device__ float  g_invdeg[Nn];
__device__ int    g_bsum[NB_SCAN];

// ---------------------------------------------------------------------------
__global__ void zero_deg_kernel() {
    int i = blockIdx.x * blockDim.x + threadIdx.x;
    if (i < Nn) g_deg[i] = 0;
}

__global__ void deg_kernel(const int* __restrict__ dst) {
    int e4 = blockIdx.x * blockDim.x + threadIdx.x;
    if (e4 < Ed / 4) {
        int4 d = __ldg(reinterpret_cast<const int4*>(dst) + e4);
        atomicAdd(&g_deg[d.x], 1);
        atomicAdd(&g_deg[d.y], 1);
        atomicAdd(&g_deg[d.z], 1);
        atomicAdd(&g_deg[d.w], 1);
    }
}

// warp-shuffle block scan; invdeg fused
__global__ void scanA_kernel() {
    __shared__ int wsum[32];
    int tid = threadIdx.x;
    int i = blockIdx.x * 1024 + tid;
    int v = (i < Nn) ? g_deg[i] : 0;
    if (i < Nn) g_invdeg[i] = 1.0f / fmaxf((float)v, 1.0f);
    int lane = tid & 31, wid = tid >> 5;
    int x = v;
#pragma unroll
    for (int o = 1; o < 32; o <<= 1) {
        int t = __shfl_up_sync(0xFFFFFFFFu, x, o);
        if (lane >= o) x += t;
    }
    if (lane == 31) wsum[wid] = x;
    __syncthreads();
    if (wid == 0) {
        int s = wsum[lane];
#pragma unroll
        for (int o = 1; o < 32; o <<= 1) {
            int t = __shfl_up_sync(0xFFFFFFFFu, s, o);
            if (lane >= o) s += t;
        }
        wsum[lane] = s;
    }
    __syncthreads();
    int incl = x + ((wid > 0) ? wsum[wid - 1] : 0);
    if (i < Nn) g_rowloc[i] = incl - v;
    if (tid == 1023) g_bsum[blockIdx.x] = incl;
}

__global__ void scanC_kernel() {
    __shared__ int sb[NB_SCAN];
    int tid = threadIdx.x;
    for (int j = tid; j < NB_SCAN; j += 256) sb[j] = g_bsum[j];
    __syncthreads();
    int i = blockIdx.x * 256 + tid;
    if (i < Nn) {
        int blk = i >> 10;
        int off = 0;
        for (int j = 0; j < blk; j++) off += sb[j];
        int r = g_rowloc[i] + off;
        g_rowptr[i] = r;
        g_cursor[i] = r;
    }
}

__global__ void fill_kernel(const int* __restrict__ src,
                            const int* __restrict__ dst) {
    int e4 = blockIdx.x * blockDim.x + threadIdx.x;
    if (e4 < Ed / 4) {
        int4 s = __ldg(reinterpret_cast<const int4*>(src) + e4);
        int4 d = __ldg(reinterpret_cast<const int4*>(dst) + e4);
        g_csr_src[atomicAdd(&g_cursor[d.x], 1)] = s.x;
        g_csr_src[atomicAdd(&g_cursor[d.y], 1)] = s.y;
        g_csr_src[atomicAdd(&g_cursor[d.z], 1)] = s.z;
        g_csr_src[atomicAdd(&g_cursor[d.w], 1)] = s.w;
    }
}

// ---------------------------------------------------------------------------
__device__ __forceinline__ uint32_t f2tf32(float x) {
    uint32_t r;
    asm("cvt.rna.tf32.f32 %0, %1;" : "=r"(r) : "f"(x));
    return r;
}

__device__ __forceinline__ void mma_tf32(float c[4], const uint32_t a[4],
                                         const uint32_t b0, const uint32_t b1) {
    asm volatile(
        "mma.sync.aligned.m16n8k8.row.col.f32.tf32.tf32.f32 "
        "{%0,%1,%2,%3}, {%4,%5,%6,%7}, {%8,%9}, {%0,%1,%2,%3};"
        : "+f"(c[0]), "+f"(c[1]), "+f"(c[2]), "+f"(c[3])
        : "r"(a[0]), "r"(a[1]), "r"(a[2]), "r"(a[3]), "r"(b0), "r"(b1));
}

__device__ __forceinline__ uint32_t s2u(const void* p) {
    uint32_t a;
    asm("{.reg .u64 t; cvta.to.shared.u64 t, %1; cvt.u32.u64 %0, t;}"
        : "=r"(a) : "l"(p));
    return a;
}

__device__ __forceinline__ void cp16(uint32_t dst, const void* src) {
    asm volatile("cp.async.cg.shared.global [%0], [%1], 16;"
                 :: "r"(dst), "l"(src));
}

// ---------------------------------------------------------------------------
// Transform via tf32 tensor cores; input TIN in {float, __half}.
// ---------------------------------------------------------------------------
template <int DOUT, typename TIN>
__global__ void transform_mma(const TIN* __restrict__ hin,
                              const float* __restrict__ Wl,
                              const float* __restrict__ bl,
                              const float* __restrict__ Wr,
                              __half* __restrict__ y,
                              __half* __restrict__ p) {
    constexpr bool IN_HALF = (sizeof(TIN) == 2);
    constexpr int NC  = 2 * DOUT;
    constexpr int NT  = NC / 8;
    constexpr int NQ  = NT / 2;
    constexpr int SHPB   = IN_HALF ? 144 : 272;
    constexpr int CHUNKS = IN_HALF ? 8 : 16;
    constexpr int WF_WORDS = 8 * NQ * 32 * 4;

    extern __shared__ uint32_t smem[];
    uint32_t* sWf = smem;
    char* sHA = (char*)(smem + WF_WORDS);
    char* sHB = sHA + 128 * SHPB;
    float* sbl = (float*)(sHB + 128 * SHPB);

    const int tid = threadIdx.x;
    const int w   = tid >> 5;
    const int l   = tid & 31;
    const int g   = l >> 2;
    const int tig = l & 3;

    for (int idx = tid; idx < 8 * NQ * 32; idx += 256) {
        int ks  = idx / (NQ * 32);
        int rem = idx - ks * (NQ * 32);
        int q   = rem >> 5;
        int ll  = rem & 31;
        int gg  = ll >> 2;
        int tt  = ll & 3;
        int k_lo = ks * 8 + tt;
        int k_hi = k_lo + 4;
        uint4 frag;
        {
            int cc = (2 * q) * 8 + gg;
            const float* basev = (cc < DOUT) ? (Wl + cc) : (Wr + cc - DOUT);
            frag.x = f2tf32(__ldg(basev + k_lo * DOUT));
            frag.y = f2tf32(__ldg(basev + k_hi * DOUT));
        }
        {
            int cc = (2 * q + 1) * 8 + gg;
            const float* basev = (cc < DOUT) ? (Wl + cc) : (Wr + cc - DOUT);
            frag.z = f2tf32(__ldg(basev + k_lo * DOUT));
            frag.w = f2tf32(__ldg(basev + k_hi * DOUT));
        }
        reinterpret_cast<uint4*>(sWf)[idx] = frag;
    }
    if (tid < DOUT) sbl[tid] = bl[tid];

    const uint4* wf = reinterpret_cast<const uint4*>(sWf) + l;

    auto stage = [&](int tile, char* buf) {
        if (tile < NTILES) {
            const int base = tile * 128;
            const uint32_t bufu = s2u(buf);
            for (int v = tid; v < 128 * CHUNKS; v += 256) {
                int r  = v / CHUNKS;
                int cb = (v - r * CHUNKS) * 16;
                int node = base + r;
                uint32_t d = bufu + (uint32_t)(r * SHPB + cb);
                if (node < Nn)
                    cp16(d, (const char*)(hin + (size_t)node * 64) + cb);
                else
                    *reinterpret_cast<uint4*>(buf + r * SHPB + cb) =
                        make_uint4(0, 0, 0, 0);
            }
        }
        asm volatile("cp.async.commit_group;");
    };

    char* cur = sHA;
    char* nxt = sHB;
    int tile = blockIdx.x;
    stage(tile, cur);

    for (; tile < NTILES; tile += gridDim.x) {
        stage(tile + gridDim.x, nxt);
        asm volatile("cp.async.wait_group 1;");
        __syncthreads();

        float c[NT][4];
#pragma unroll
        for (int nt = 0; nt < NT; nt++) {
            c[nt][0] = 0.f; c[nt][1] = 0.f; c[nt][2] = 0.f; c[nt][3] = 0.f;
        }

        const char* rp0 = cur + (16 * w + g) * SHPB;
        const char* rp1 = rp0 + 8 * SHPB;

#pragma unroll
        for (int ks = 0; ks < 8; ks++) {
            const int k0 = ks * 8;
            uint32_t a[4];
            if (IN_HALF) {
                const __half* h0r = (const __half*)rp0;
                const __half* h1r = (const __half*)rp1;
                a[0] = f2tf32(__half2float(h0r[k0 + tig]));
                a[1] = f2tf32(__half2float(h1r[k0 + tig]));
                a[2] = f2tf32(__half2float(h0r[k0 + tig + 4]));
                a[3] = f2tf32(__half2float(h1r[k0 + tig + 4]));
            } else {
                const float* f0r = (const float*)rp0;
                const float* f1r = (const float*)rp1;
                a[0] = f2tf32(f0r[k0 + tig]);
                a[1] = f2tf32(f1r[k0 + tig]);
                a[2] = f2tf32(f0r[k0 + tig + 4]);
                a[3] = f2tf32(f1r[k0 + tig + 4]);
            }
#pragma unroll
            for (int q = 0; q < NQ; q++) {
                uint4 b = wf[(ks * NQ + q) * 32];
                mma_tf32(c[2 * q],     a, b.x, b.y);
                mma_tf32(c[2 * q + 1], a, b.z, b.w);
            }
        }

        const int base = tile * 128;
        const int node0 = base + 16 * w + g;
        const int node1 = node0 + 8;
#pragma unroll
        for (int nt = 0; nt < NT; nt++) {
            int col = nt * 8 + 2 * tig;
            if (col < DOUT) {
                if (node0 < Nn)
                    *reinterpret_cast<__half2*>(y + (size_t)node0 * DOUT + col) =
                        __floats2half2_rn(c[nt][0], c[nt][1]);
                if (node1 < Nn)
                    *reinterpret_cast<__half2*>(y + (size_t)node1 * DOUT + col) =
                        __floats2half2_rn(c[nt][2], c[nt][3]);
            } else {
                int pc = col - DOUT;
                float b0 = sbl[pc], b1 = sbl[pc + 1];
                if (node0 < Nn)
                    *reinterpret_cast<__half2*>(p + (size_t)node0 * DOUT + pc) =
                        __floats2half2_rn(c[nt][0] + b0, c[nt][1] + b1);
                if (node1 < Nn)
                    *reinterpret_cast<__half2*>(p + (size_t)node1 * DOUT + pc) =
                        __floats2half2_rn(c[nt][2] + b0, c[nt][3] + b1);
            }
        }
        __syncthreads();
        char* t = cur; cur = nxt; nxt = t;
    }
}

// ---------------------------------------------------------------------------
// Gather, TWO nodes per warp: lanes 0-15 -> node 2w, lanes 16-31 -> node 2w+1.
// Each lane covers 4 dims (uint2 = 2x half2). One row-LDG instruction fetches
// rows for both nodes; one index-LDG serves both halves -> ~2x fewer LSU issues.
// ---------------------------------------------------------------------------
template <int DOUT, bool RELU, bool FINAL>
__global__ void gather_kernel(const __half* __restrict__ y,
                              const __half* __restrict__ p,
                              void* __restrict__ outv) {
    int gw   = (blockIdx.x * blockDim.x + threadIdx.x) >> 5;
    int lane = threadIdx.x & 31;
    int half = lane >> 4;
    int hl   = lane & 15;
    int node = 2 * gw + half;
    if (node >= Nn) return;
    const bool act = (4 * hl) < DOUT;

    const int start = g_rowptr[node];
    const int cnt   = g_deg[node];
    const int* __restrict__ idxp = g_csr_src + start;

    float4 acc = make_float4(0.f, 0.f, 0.f, 0.f);

    auto addrow = [&](int s) {
        uint2 v = __ldg(reinterpret_cast<const uint2*>(y + (size_t)s * DOUT) + hl);
        float2 lo = __half22float2(*reinterpret_cast<__half2*>(&v.x));
        float2 hi = __half22float2(*reinterpret_cast<__half2*>(&v.y));
        acc.x += lo.x; acc.y += lo.y; acc.z += hi.x; acc.w += hi.y;
    };

    int i = 0;
    for (; i + 8 <= cnt; i += 8) {
        int s0 = __ldg(idxp + i + 0);
        int s1 = __ldg(idxp + i + 1);
        int s2 = __ldg(idxp + i + 2);
        int s3 = __ldg(idxp + i + 3);
        int s4 = __ldg(idxp + i + 4);
        int s5 = __ldg(idxp + i + 5);
        int s6 = __ldg(idxp + i + 6);
        int s7 = __ldg(idxp + i + 7);
        if (act) {
            addrow(s0); addrow(s1); addrow(s2); addrow(s3);
            addrow(s4); addrow(s5); addrow(s6); addrow(s7);
        }
    }
    for (; i < cnt; i++) {
        int s = __ldg(idxp + i);
        if (act) addrow(s);
    }

    float invd = g_invdeg[node];
    float4 o = make_float4(0.f, 0.f, 0.f, 0.f);
    if (act) {
        uint2 pv = __ldg(reinterpret_cast<const uint2*>(p + (size_t)node * DOUT) + hl);
        float2 plo = __half22float2(*reinterpret_cast<__half2*>(&pv.x));
        float2 phi = __half22float2(*reinterpret_cast<__half2*>(&pv.y));
        o.x = fmaf(acc.x, invd, plo.x);
        o.y = fmaf(acc.y, invd, plo.y);
        o.z = fmaf(acc.z, invd, phi.x);
        o.w = fmaf(acc.w, invd, phi.y);
        if (RELU) {
            o.x = fmaxf(o.x, 0.f); o.y = fmaxf(o.y, 0.f);
            o.z = fmaxf(o.z, 0.f); o.w = fmaxf(o.w, 0.f);
        }
    }

    if (FINAL) {
        // log_softmax across the node's DOUT dims = reduction within half-warp
        float m = act ? fmaxf(fmaxf(o.x, o.y), fmaxf(o.z, o.w)) : -INFINITY;
#pragma unroll
        for (int off = 8; off; off >>= 1)
            m = fmaxf(m, __shfl_xor_sync(0xFFFFFFFFu, m, off, 16));
        float s = act ? (expf(o.x - m) + expf(o.y - m) + expf(o.z - m) + expf(o.w - m)) : 0.f;
#pragma unroll
        for (int off = 8; off; off >>= 1)
            s += __shfl_xor_sync(0xFFFFFFFFu, s, off, 16);
        float lse = m + logf(s);
        if (act) {
            float* out = (float*)outv;
            *reinterpret_cast<float4*>(out + (size_t)node * DOUT + 4 * hl) =
                make_float4(o.x - lse, o.y - lse, o.z - lse, o.w - lse);
        }
    } else {
        if (act) {
            __half* out = (__half*)outv;
            uint2 pk;
            __half2 a01 = __floats2half2_rn(o.x, o.y);
            __half2 a23 = __floats2half2_rn(o.z, o.w);
            pk.x = *reinterpret_cast<uint32_t*>(&a01);
            pk.y = *reinterpret_cast<uint32_t*>(&a23);
            *reinterpret_cast<uint2*>(out + (size_t)node * DOUT + 4 * hl) = pk;
        }
    }
}

// ---------------------------------------------------------------------------
extern "C" void kernel_launch(void* const* d_in, const int* in_sizes, int n_in,
                              void* d_out, int out_size) {
    const float* x   = (const float*)d_in[0];
    const int*   ei  = (const int*)d_in[1];
    const int*   src = ei;
    const int*   dst = ei + Ed;
    const float* Wl0 = (const float*)d_in[2];
    const float* bl0 = (const float*)d_in[3];
    const float* Wr0 = (const float*)d_in[4];
    const float* Wl1 = (const float*)d_in[5];
    const float* bl1 = (const float*)d_in[6];
    const float* Wr1 = (const float*)d_in[7];
    const float* Wl2 = (const float*)d_in[8];
    const float* bl2 = (const float*)d_in[9];
    const float* Wr2 = (const float*)d_in[10];

    __half *yp, *pp, *h0p, *h1p;
    cudaGetSymbolAddress((void**)&yp,  g_y);
    cudaGetSymbolAddress((void**)&pp,  g_p);
    cudaGetSymbolAddress((void**)&h0p, g_h0);
    cudaGetSymbolAddress((void**)&h1p, g_h1);

    const int ngrid  = (Nn + 255) / 256;
    const int e4grid = (Ed / 4 + 255) / 256;
    // two nodes per warp: ceil(Nn/2) warps
    const int ggrid  = (((Nn + 1) / 2) * 32 + 255) / 256;

    const int smem64f = (8 * 8 * 32 * 4) * 4 + 2 * 128 * 272 + 64 * 4;
    const int smem64h = (8 * 8 * 32 * 4) * 4 + 2 * 128 * 144 + 64 * 4;
    const int smem40h = (8 * 5 * 32 * 4) * 4 + 2 * 128 * 144 + 40 * 4;
    cudaFuncSetAttribute((const void*)transform_mma<64, float>,
                         cudaFuncAttributeMaxDynamicSharedMemorySize, smem64f);
    cudaFuncSetAttribute((const void*)transform_mma<64, __half>,
                         cudaFuncAttributeMaxDynamicSharedMemorySize, smem64h);
    cudaFuncSetAttribute((const void*)transform_mma<40, __half>,
                         cudaFuncAttributeMaxDynamicSharedMemorySize, smem40h);

    const int tgrid = 296;

    static cudaStream_t s2 = nullptr;
    static cudaEvent_t evFork = nullptr, evJoin = nullptr;
    if (s2 == nullptr) {
        cudaStreamCreateWithFlags(&s2, cudaStreamNonBlocking);
        cudaEventCreateWithFlags(&evFork, cudaEventDisableTiming);
        cudaEventCreateWithFlags(&evJoin, cudaEventDisableTiming);
    }

    // ---- Fork: T0 on s2 overlaps CSR build on stream 0 ----
    cudaEventRecord(evFork, 0);
    cudaStreamWaitEvent(s2, evFork, 0);
    transform_mma<64, float><<<tgrid, 256, smem64f, s2>>>(x, Wl0, bl0, Wr0, yp, pp);
    cudaEventRecord(evJoin, s2);

    zero_deg_kernel<<<ngrid, 256>>>();
    deg_kernel<<<e4grid, 256>>>(dst);
    scanA_kernel<<<NB_SCAN, 1024>>>();
    scanC_kernel<<<ngrid, 256>>>();
    fill_kernel<<<e4grid, 256>>>(src, dst);
    cudaStreamWaitEvent(0, evJoin, 0);

    // ---- Layer 0 gather ----
    gather_kernel<64, true, false><<<ggrid, 256>>>(yp, pp, h0p);

    // ---- Layer 1 ----
    transform_mma<64, __half><<<tgrid, 256, smem64h>>>(h0p, Wl1, bl1, Wr1, yp, pp);
    gather_kernel<64, true, false><<<ggrid, 256>>>(yp, pp, h1p);

    // ---- Layer 2 (gather fused with log_softmax) ----
    transform_mma<40, __half><<<tgrid, 256, smem40h>>>(h1p, Wl2, bl2, Wr2, yp, pp);
    gather_kernel<40, false, true><<<ggrid, 256>>>(yp, pp, d_out);
}

// round 13
// speedup vs baseline: 1.2185x; 1.0233x over previous
#include <cuda_runtime.h>
#include <cuda_fp16.h>
#include <math.h>
#include <stdint.h>

constexpr int Nn = 100000;
constexpr int Ed = 1600000;
constexpr int DIN = 64;
constexpr int NB_SCAN = (Nn + 1023) / 1024;   // 98
constexpr int NTILES  = (Nn + 127) / 128;     // 782

// ---- scratch (device globals; no allocation allowed) ----------------------
__device__ __half g_y[(size_t)Nn * 64];       // h @ Wl           (fp16)
__device__ __half g_p[(size_t)Nn * 64];       // h @ Wr + bl      (fp16)
__device__ __half g_h0[(size_t)Nn * 64];      // layer outputs    (fp16)
__device__ __half g_h1[(size_t)Nn * 64];
__device__ int    g_csr_src[Ed];
__device__ int    g_rowptr[Nn];
__device__ int    g_rowloc[Nn];
__device__ int    g_cursor[Nn];
__device__ int    g_deg[Nn];
__device__ float  g_invdeg[Nn];
__device__ int    g_bsum[NB_SCAN];

// ---------------------------------------------------------------------------
__global__ void zero_deg_kernel() {
    int i = blockIdx.x * blockDim.x + threadIdx.x;
    if (i < Nn) g_deg[i] = 0;
}

__global__ void deg_kernel(const int* __restrict__ dst) {
    int e4 = blockIdx.x * blockDim.x + threadIdx.x;
    if (e4 < Ed / 4) {
        int4 d = __ldg(reinterpret_cast<const int4*>(dst) + e4);
        atomicAdd(&g_deg[d.x], 1);
        atomicAdd(&g_deg[d.y], 1);
        atomicAdd(&g_deg[d.z], 1);
        atomicAdd(&g_deg[d.w], 1);
    }
}

// warp-shuffle block scan; invdeg fused
__global__ void scanA_kernel() {
    __shared__ int wsum[32];
    int tid = threadIdx.x;
    int i = blockIdx.x * 1024 + tid;
    int v = (i < Nn) ? g_deg[i] : 0;
    if (i < Nn) g_invdeg[i] = 1.0f / fmaxf((float)v, 1.0f);
    int lane = tid & 31, wid = tid >> 5;
    int x = v;
#pragma unroll
    for (int o = 1; o < 32; o <<= 1) {
        int t = __shfl_up_sync(0xFFFFFFFFu, x, o);
        if (lane >= o) x += t;
    }
    if (lane == 31) wsum[wid] = x;
    __syncthreads();
    if (wid == 0) {
        int s = wsum[lane];
#pragma unroll
        for (int o = 1; o < 32; o <<= 1) {
            int t = __shfl_up_sync(0xFFFFFFFFu, s, o);
            if (lane >= o) s += t;
        }
        wsum[lane] = s;
    }
    __syncthreads();
    int incl = x + ((wid > 0) ? wsum[wid - 1] : 0);
    if (i < Nn) g_rowloc[i] = incl - v;
    if (tid == 1023) g_bsum[blockIdx.x] = incl;
}

__global__ void scanC_kernel() {
    __shared__ int sb[NB_SCAN];
    int tid = threadIdx.x;
    for (int j = tid; j < NB_SCAN; j += 256) sb[j] = g_bsum[j];
    __syncthreads();
    int i = blockIdx.x * 256 + tid;
    if (i < Nn) {
        int blk = i >> 10;
        int off = 0;
        for (int j = 0; j < blk; j++) off += sb[j];
        int r = g_rowloc[i] + off;
        g_rowptr[i] = r;
        g_cursor[i] = r;
    }
}

__global__ void fill_kernel(const int* __restrict__ src,
                            const int* __restrict__ dst) {
    int e4 = blockIdx.x * blockDim.x + threadIdx.x;
    if (e4 < Ed / 4) {
        int4 s = __ldg(reinterpret_cast<const int4*>(src) + e4);
        int4 d = __ldg(reinterpret_cast<const int4*>(dst) + e4);
        g_csr_src[atomicAdd(&g_cursor[d.x], 1)] = s.x;
        g_csr_src[atomicAdd(&g_cursor[d.y], 1)] = s.y;
        g_csr_src[atomicAdd(&g_cursor[d.z], 1)] = s.z;
        g_csr_src[atomicAdd(&g_cursor[d.w], 1)] = s.w;
    }
}

// ---------------------------------------------------------------------------
__device__ __forceinline__ uint32_t f2tf32(float x) {
    uint32_t r;
    asm("cvt.rna.tf32.f32 %0, %1;" : "=r"(r) : "f"(x));
    return r;
}

__device__ __forceinline__ void mma_tf32(float c[4], const uint32_t a[4],
                                         const uint32_t b0, const uint32_t b1) {
    asm volatile(
        "mma.sync.aligned.m16n8k8.row.col.f32.tf32.tf32.f32 "
        "{%0,%1,%2,%3}, {%4,%5,%6,%7}, {%8,%9}, {%0,%1,%2,%3};"
        : "+f"(c[0]), "+f"(c[1]), "+f"(c[2]), "+f"(c[3])
        : "r"(a[0]), "r"(a[1]), "r"(a[2]), "r"(a[3]), "r"(b0), "r"(b1));
}

__device__ __forceinline__ uint32_t s2u(const void* p) {
    uint32_t a;
    asm("{.reg .u64 t; cvta.to.shared.u64 t, %1; cvt.u32.u64 %0, t;}"
        : "=r"(a) : "l"(p));
    return a;
}

__device__ __forceinline__ void cp16(uint32_t dst, const void* src) {
    asm volatile("cp.async.cg.shared.global [%0], [%1], 16;"
                 :: "r"(dst), "l"(src));
}

// ---------------------------------------------------------------------------
// Transform via tf32 tensor cores; input TIN in {float, __half}.
// ---------------------------------------------------------------------------
template <int DOUT, typename TIN>
__global__ void transform_mma(const TIN* __restrict__ hin,
                              const float* __restrict__ Wl,
                              const float* __restrict__ bl,
                              const float* __restrict__ Wr,
                              __half* __restrict__ y,
                              __half* __restrict__ p) {
    constexpr bool IN_HALF = (sizeof(TIN) == 2);
    constexpr int NC  = 2 * DOUT;
    constexpr int NT  = NC / 8;
    constexpr int NQ  = NT / 2;
    constexpr int SHPB   = IN_HALF ? 144 : 272;
    constexpr int CHUNKS = IN_HALF ? 8 : 16;
    constexpr int WF_WORDS = 8 * NQ * 32 * 4;

    extern __shared__ uint32_t smem[];
    uint32_t* sWf = smem;
    char* sHA = (char*)(smem + WF_WORDS);
    char* sHB = sHA + 128 * SHPB;
    float* sbl = (float*)(sHB + 128 * SHPB);

    const int tid = threadIdx.x;
    const int w   = tid >> 5;
    const int l   = tid & 31;
    const int g   = l >> 2;
    const int tig = l & 3;

    for (int idx = tid; idx < 8 * NQ * 32; idx += 256) {
        int ks  = idx / (NQ * 32);
        int rem = idx - ks * (NQ * 32);
        int q   = rem >> 5;
        int ll  = rem & 31;
        int gg  = ll >> 2;
        int tt  = ll & 3;
        int k_lo = ks * 8 + tt;
        int k_hi = k_lo + 4;
        uint4 frag;
        {
            int cc = (2 * q) * 8 + gg;
            const float* basev = (cc < DOUT) ? (Wl + cc) : (Wr + cc - DOUT);
            frag.x = f2tf32(__ldg(basev + k_lo * DOUT));
            frag.y = f2tf32(__ldg(basev + k_hi * DOUT));
        }
        {
            int cc = (2 * q + 1) * 8 + gg;
            const float* basev = (cc < DOUT) ? (Wl + cc) : (Wr + cc - DOUT);
            frag.z = f2tf32(__ldg(basev + k_lo * DOUT));
            frag.w = f2tf32(__ldg(basev + k_hi * DOUT));
        }
        reinterpret_cast<uint4*>(sWf)[idx] = frag;
    }
    if (tid < DOUT) sbl[tid] = bl[tid];

    const uint4* wf = reinterpret_cast<const uint4*>(sWf) + l;

    auto stage = [&](int tile, char* buf) {
        if (tile < NTILES) {
            const int base = tile * 128;
            const uint32_t bufu = s2u(buf);
            for (int v = tid; v < 128 * CHUNKS; v += 256) {
                int r  = v / CHUNKS;
                int cb = (v - r * CHUNKS) * 16;
                int node = base + r;
                uint32_t d = bufu + (uint32_t)(r * SHPB + cb);
                if (node < Nn)
                    cp16(d, (const char*)(hin + (size_t)node * 64) + cb);
                else
                    *reinterpret_cast<uint4*>(buf + r * SHPB + cb) =
                        make_uint4(0, 0, 0, 0);
            }
        }
        asm volatile("cp.async.commit_group;");
    };

    char* cur = sHA;
    char* nxt = sHB;
    int tile = blockIdx.x;
    stage(tile, cur);

    for (; tile < NTILES; tile += gridDim.x) {
        stage(tile + gridDim.x, nxt);
        asm volatile("cp.async.wait_group 1;");
        __syncthreads();

        float c[NT][4];
#pragma unroll
        for (int nt = 0; nt < NT; nt++) {
            c[nt][0] = 0.f; c[nt][1] = 0.f; c[nt][2] = 0.f; c[nt][3] = 0.f;
        }

        const char* rp0 = cur + (16 * w + g) * SHPB;
        const char* rp1 = rp0 + 8 * SHPB;

#pragma unroll
        for (int ks = 0; ks < 8; ks++) {
            const int k0 = ks * 8;
            uint32_t a[4];
            if (IN_HALF) {
                const __half* h0r = (const __half*)rp0;
                const __half* h1r = (const __half*)rp1;
                a[0] = f2tf32(__half2float(h0r[k0 + tig]));
                a[1] = f2tf32(__half2float(h1r[k0 + tig]));
                a[2] = f2tf32(__half2float(h0r[k0 + tig + 4]));
                a[3] = f2tf32(__half2float(h1r[k0 + tig + 4]));
            } else {
                const float* f0r = (const float*)rp0;
                const float* f1r = (const float*)rp1;
                a[0] = f2tf32(f0r[k0 + tig]);
                a[1] = f2tf32(f1r[k0 + tig]);
                a[2] = f2tf32(f0r[k0 + tig + 4]);
                a[3] = f2tf32(f1r[k0 + tig + 4]);
            }
#pragma unroll
            for (int q = 0; q < NQ; q++) {
                uint4 b = wf[(ks * NQ + q) * 32];
                mma_tf32(c[2 * q],     a, b.x, b.y);
                mma_tf32(c[2 * q + 1], a, b.z, b.w);
            }
        }

        const int base = tile * 128;
        const int node0 = base + 16 * w + g;
        const int node1 = node0 + 8;
#pragma unroll
        for (int nt = 0; nt < NT; nt++) {
            int col = nt * 8 + 2 * tig;
            if (col < DOUT) {
                if (node0 < Nn)
                    *reinterpret_cast<__half2*>(y + (size_t)node0 * DOUT + col) =
                        __floats2half2_rn(c[nt][0], c[nt][1]);
                if (node1 < Nn)
                    *reinterpret_cast<__half2*>(y + (size_t)node1 * DOUT + col) =
                        __floats2half2_rn(c[nt][2], c[nt][3]);
            } else {
                int pc = col - DOUT;
                float b0 = sbl[pc], b1 = sbl[pc + 1];
                if (node0 < Nn)
                    *reinterpret_cast<__half2*>(p + (size_t)node0 * DOUT + pc) =
                        __floats2half2_rn(c[nt][0] + b0, c[nt][1] + b1);
                if (node1 < Nn)
                    *reinterpret_cast<__half2*>(p + (size_t)node1 * DOUT + pc) =
                        __floats2half2_rn(c[nt][2] + b0, c[nt][3] + b1);
            }
        }
        __syncthreads();
        char* t = cur; cur = nxt; nxt = t;
    }
}

// ---------------------------------------------------------------------------
// Gather, FOUR nodes per warp: 8-lane group q serves node 4w+q.
// Each lane covers 8 dims via one uint4 (16 B); 8 lanes = full 128 B row.
// One row-LDG instruction fetches rows for 4 nodes; one index-LDG serves all.
// ---------------------------------------------------------------------------
template <int DOUT, bool RELU, bool FINAL>
__global__ void gather_kernel(const __half* __restrict__ y,
                              const __half* __restrict__ p,
                              void* __restrict__ outv) {
    int gw   = (blockIdx.x * blockDim.x + threadIdx.x) >> 5;
    int lane = threadIdx.x & 31;
    int qu   = lane >> 3;          // group 0..3
    int ql   = lane & 7;           // lane within group
    int node = 4 * gw + qu;
    if (node >= Nn) return;
    const bool act = (8 * ql) < DOUT;

    const int start = g_rowptr[node];
    const int cnt   = g_deg[node];
    const int* __restrict__ idxp = g_csr_src + start;

    float acc[8];
#pragma unroll
    for (int k = 0; k < 8; k++) acc[k] = 0.f;

    auto addrow = [&](int s) {
        uint4 v = __ldg(reinterpret_cast<const uint4*>(y + (size_t)s * DOUT) + ql);
        float2 f0 = __half22float2(*reinterpret_cast<__half2*>(&v.x));
        float2 f1 = __half22float2(*reinterpret_cast<__half2*>(&v.y));
        float2 f2 = __half22float2(*reinterpret_cast<__half2*>(&v.z));
        float2 f3 = __half22float2(*reinterpret_cast<__half2*>(&v.w));
        acc[0] += f0.x; acc[1] += f0.y; acc[2] += f1.x; acc[3] += f1.y;
        acc[4] += f2.x; acc[5] += f2.y; acc[6] += f3.x; acc[7] += f3.y;
    };

    int i = 0;
    for (; i + 8 <= cnt; i += 8) {
        int s0 = __ldg(idxp + i + 0);
        int s1 = __ldg(idxp + i + 1);
        int s2 = __ldg(idxp + i + 2);
        int s3 = __ldg(idxp + i + 3);
        int s4 = __ldg(idxp + i + 4);
        int s5 = __ldg(idxp + i + 5);
        int s6 = __ldg(idxp + i + 6);
        int s7 = __ldg(idxp + i + 7);
        if (act) {
            addrow(s0); addrow(s1); addrow(s2); addrow(s3);
            addrow(s4); addrow(s5); addrow(s6); addrow(s7);
        }
    }
    for (; i < cnt; i++) {
        int s = __ldg(idxp + i);
        if (act) addrow(s);
    }

    float invd = g_invdeg[node];
    float o[8];
#pragma unroll
    for (int k = 0; k < 8; k++) o[k] = 0.f;
    if (act) {
        uint4 pv = __ldg(reinterpret_cast<const uint4*>(p + (size_t)node * DOUT) + ql);
        float2 p0 = __half22float2(*reinterpret_cast<__half2*>(&pv.x));
        float2 p1 = __half22float2(*reinterpret_cast<__half2*>(&pv.y));
        float2 p2 = __half22float2(*reinterpret_cast<__half2*>(&pv.z));
        float2 p3 = __half22float2(*reinterpret_cast<__half2*>(&pv.w));
        float pf[8] = {p0.x, p0.y, p1.x, p1.y, p2.x, p2.y, p3.x, p3.y};
#pragma unroll
        for (int k = 0; k < 8; k++) {
            o[k] = fmaf(acc[k], invd, pf[k]);
            if (RELU) o[k] = fmaxf(o[k], 0.f);
        }
    }

    if (FINAL) {
        // log_softmax across DOUT dims = reduction within 8-lane group
        float m = -INFINITY;
        if (act) {
#pragma unroll
            for (int k = 0; k < 8; k++) m = fmaxf(m, o[k]);
        }
#pragma unroll
        for (int off = 4; off; off >>= 1)
            m = fmaxf(m, __shfl_xor_sync(0xFFFFFFFFu, m, off, 8));
        float s = 0.f;
        if (act) {
#pragma unroll
            for (int k = 0; k < 8; k++) s += expf(o[k] - m);
        }
#pragma unroll
        for (int off = 4; off; off >>= 1)
            s += __shfl_xor_sync(0xFFFFFFFFu, s, off, 8);
        float lse = m + logf(s);
        if (act) {
            float* out = (float*)outv + (size_t)node * DOUT + 8 * ql;
            *reinterpret_cast<float4*>(out) =
                make_float4(o[0] - lse, o[1] - lse, o[2] - lse, o[3] - lse);
            *reinterpret_cast<float4*>(out + 4) =
                make_float4(o[4] - lse, o[5] - lse, o[6] - lse, o[7] - lse);
        }
    } else {
        if (act) {
            __half* out = (__half*)outv;
            uint4 pk;
            __half2 a01 = __floats2half2_rn(o[0], o[1]);
            __half2 a23 = __floats2half2_rn(o[2], o[3]);
            __half2 a45 = __floats2half2_rn(o[4], o[5]);
            __half2 a67 = __floats2half2_rn(o[6], o[7]);
            pk.x = *reinterpret_cast<uint32_t*>(&a01);
            pk.y = *reinterpret_cast<uint32_t*>(&a23);
            pk.z = *reinterpret_cast<uint32_t*>(&a45);
            pk.w = *reinterpret_cast<uint32_t*>(&a67);
            *reinterpret_cast<uint4*>(out + (size_t)node * DOUT + 8 * ql) = pk;
        }
    }
}

// ---------------------------------------------------------------------------
extern "C" void kernel_launch(void* const* d_in, const int* in_sizes, int n_in,
                              void* d_out, int out_size) {
    const float* x   = (const float*)d_in[0];
    const int*   ei  = (const int*)d_in[1];
    const int*   src = ei;
    const int*   dst = ei + Ed;
    const float* Wl0 = (const float*)d_in[2];
    const float* bl0 = (const float*)d_in[3];
    const float* Wr0 = (const float*)d_in[4];
    const float* Wl1 = (const float*)d_in[5];
    const float* bl1 = (const float*)d_in[6];
    const float* Wr1 = (const float*)d_in[7];
    const float* Wl2 = (const float*)d_in[8];
    const float* bl2 = (const float*)d_in[9];
    const float* Wr2 = (const float*)d_in[10];

    __half *yp, *pp, *h0p, *h1p;
    cudaGetSymbolAddress((void**)&yp,  g_y);
    cudaGetSymbolAddress((void**)&pp,  g_p);
    cudaGetSymbolAddress((void**)&h0p, g_h0);
    cudaGetSymbolAddress((void**)&h1p, g_h1);

    const int ngrid  = (Nn + 255) / 256;
    const int e4grid = (Ed / 4 + 255) / 256;
    // four nodes per warp: ceil(Nn/4) warps
    const int ggrid  = (((Nn + 3) / 4) * 32 + 255) / 256;

    const int smem64f = (8 * 8 * 32 * 4) * 4 + 2 * 128 * 272 + 64 * 4;
    const int smem64h = (8 * 8 * 32 * 4) * 4 + 2 * 128 * 144 + 64 * 4;
    const int smem40h = (8 * 5 * 32 * 4) * 4 + 2 * 128 * 144 + 40 * 4;
    cudaFuncSetAttribute((const void*)transform_mma<64, float>,
                         cudaFuncAttributeMaxDynamicSharedMemorySize, smem64f);
    cudaFuncSetAttribute((const void*)transform_mma<64, __half>,
                         cudaFuncAttributeMaxDynamicSharedMemorySize, smem64h);
    cudaFuncSetAttribute((const void*)transform_mma<40, __half>,
                         cudaFuncAttributeMaxDynamicSharedMemorySize, smem40h);

    const int tgrid = 296;

    static cudaStream_t s2 = nullptr;
    static cudaEvent_t evFork = nullptr, evJoin = nullptr;
    if (s2 == nullptr) {
        cudaStreamCreateWithFlags(&s2, cudaStreamNonBlocking);
        cudaEventCreateWithFlags(&evFork, cudaEventDisableTiming);
        cudaEventCreateWithFlags(&evJoin, cudaEventDisableTiming);
    }

    // ---- Fork: T0 on s2 overlaps CSR build on stream 0 ----
    cudaEventRecord(evFork, 0);
    cudaStreamWaitEvent(s2, evFork, 0);
    transform_mma<64, float><<<tgrid, 256, smem64f, s2>>>(x, Wl0, bl0, Wr0, yp, pp);
    cudaEventRecord(evJoin, s2);

    zero_deg_kernel<<<ngrid, 256>>>();
    deg_kernel<<<e4grid, 256>>>(dst);
    scanA_kernel<<<NB_SCAN, 1024>>>();
    scanC_kernel<<<ngrid, 256>>>();
    fill_kernel<<<e4grid, 256>>>(src, dst);
    cudaStreamWaitEvent(0, evJoin, 0);

    // ---- Layer 0 gather ----
    gather_kernel<64, true, false><<<ggrid, 256>>>(yp, pp, h0p);

    // ---- Layer 1 ----
    transform_mma<64, __half><<<tgrid, 256, smem64h>>>(h0p, Wl1, bl1, Wr1, yp, pp);
    gather_kernel<64, true, false><<<ggrid, 256>>>(yp, pp, h1p);

    // ---- Layer 2 (gather fused with log_softmax) ----
    transform_mma<40, __half><<<tgrid, 256, smem40h>>>(h1p, Wl2, bl2, Wr2, yp, pp);
    gather_kernel<40, false, true><<<ggrid, 256>>>(yp, pp, d_out);
}